// round 7
// baseline (speedup 1.0000x reference)
#include <cuda_runtime.h>
#include <cuda_bf16.h>
#include <cstdint>
#include <math.h>

// ---------------------------------------------------------------------------
// ParallelTransformerBlock via legacy tensor-core path (mma.sync tf32 + cp.async)
// B=1, N=2048, DIM=2048, HEADS=16, DH=128, FF_INNER=8192, FUSED_OUT=18688
// R7: merged output GEMM (K=10240), ks-level fragment double buffering.
// ---------------------------------------------------------------------------

#define NSEQ 2048
#define DIM 2048
#define DH 128
#define HEADS 16
#define ATTN_INNER 2048
#define FF_INNER 8192
#define FUSED_OUT 18688
#define FF_BASE 2304      // ATTN_INNER + 2*DH
#define GATE_BASE 10496   // FF_BASE + FF_INNER
#define CAT_K (ATTN_INNER + FF_INNER)   // 10240
#define LN_EPS 1e-5f

// ------------------------- device scratch (static) -------------------------
__device__ float g_xn[(size_t)NSEQ * DIM];                    // 16 MB
__device__ float g_proj[(size_t)NSEQ * FUSED_OUT];            // 153 MB
__device__ float g_sim[(size_t)HEADS * NSEQ * NSEQ];          // 256 MB
__device__ float g_cat[(size_t)NSEQ * CAT_K];                 // 80 MB (attnc | ffact)
// tf32-rounded weight copies
__device__ float g_wf[(size_t)DIM * FUSED_OUT];               // 153 MB
__device__ float g_wcat[(size_t)CAT_K * DIM];                 // 80 MB (wao ; wfo stacked)

// --------------------------- PTX helpers -----------------------------------
__device__ __forceinline__ uint32_t smem_u32(const void* p) {
    uint32_t a;
    asm("{ .reg .u64 t; cvta.to.shared.u64 t, %1; cvt.u32.u64 %0, t; }"
        : "=r"(a) : "l"(p));
    return a;
}

__device__ __forceinline__ float tf32r(float x) {
    uint32_t u;
    asm("cvt.rna.tf32.f32 %0, %1;" : "=r"(u) : "f"(x));
    return __uint_as_float(u);
}

#define CP_ASYNC16(smaddr, gptr) \
    asm volatile("cp.async.cg.shared.global [%0], [%1], 16;" :: "r"(smaddr), "l"(gptr))
#define CP_COMMIT() asm volatile("cp.async.commit_group;" ::: "memory")
#define CP_WAIT1()  asm volatile("cp.async.wait_group 1;" ::: "memory")

__device__ __forceinline__ void mma1688(float* d, const uint32_t* a, const uint32_t* b) {
    asm volatile(
        "mma.sync.aligned.m16n8k8.row.col.f32.tf32.tf32.f32 "
        "{%0,%1,%2,%3}, {%4,%5,%6,%7}, {%8,%9}, {%0,%1,%2,%3};"
        : "+f"(d[0]), "+f"(d[1]), "+f"(d[2]), "+f"(d[3])
        : "r"(a[0]), "r"(a[1]), "r"(a[2]), "r"(a[3]), "r"(b[0]), "r"(b[1]));
}

// ------------------------------ LayerNorm ----------------------------------
__global__ __launch_bounds__(256) void ln_kernel(const float* __restrict__ x,
                                                 const float* __restrict__ gamma) {
    int row = blockIdx.x;
    int tid = threadIdx.x;
    const float4* xr = (const float4*)(x + (size_t)row * DIM);
    float4* out = (float4*)(g_xn + (size_t)row * DIM);
    const float4* g4 = (const float4*)gamma;

    float s = 0.f, sq = 0.f;
    float4 v[2];
    #pragma unroll
    for (int i = 0; i < 2; i++) {
        v[i] = xr[tid + 256 * i];
        s += v[i].x + v[i].y + v[i].z + v[i].w;
        sq += v[i].x * v[i].x + v[i].y * v[i].y + v[i].z * v[i].z + v[i].w * v[i].w;
    }
    __shared__ float red[256], red2[256];
    red[tid] = s; red2[tid] = sq;
    __syncthreads();
    for (int off = 128; off > 0; off >>= 1) {
        if (tid < off) { red[tid] += red[tid + off]; red2[tid] += red2[tid + off]; }
        __syncthreads();
    }
    float mu = red[0] * (1.0f / DIM);
    float var = red2[0] * (1.0f / DIM) - mu * mu;
    float inv = rsqrtf(var + LN_EPS);
    #pragma unroll
    for (int i = 0; i < 2; i++) {
        float4 g = g4[tid + 256 * i];
        float4 o;
        o.x = tf32r((v[i].x - mu) * inv * g.x);
        o.y = tf32r((v[i].y - mu) * inv * g.y);
        o.z = tf32r((v[i].z - mu) * inv * g.z);
        o.w = tf32r((v[i].w - mu) * inv * g.w);
        out[tid + 256 * i] = o;
    }
}

// ------------------------- weight rounding (tf32) ---------------------------
__global__ __launch_bounds__(256) void round_kernel(const float4* __restrict__ src,
                                                    float4* __restrict__ dst, size_t n4) {
    for (size_t i = (size_t)blockIdx.x * 256 + threadIdx.x; i < n4;
         i += (size_t)gridDim.x * 256) {
        float4 v = src[i];
        v.x = tf32r(v.x); v.y = tf32r(v.y); v.z = tf32r(v.z); v.w = tf32r(v.w);
        dst[i] = v;
    }
}

// ------------------------- tensor-core tf32 GEMM ----------------------------
// C[M,N] (+)= alpha * A[M,K] @ B.
//  TRANSB=false: B stored [N,K] row-major (k contiguous)  -> Bs[n][k]
//  TRANSB=true : B stored [K,N] row-major (n contiguous)  -> Bs[k][n]
// blockIdx.x = M tile (256 rows), blockIdx.y = N tile (128 cols), z = batch.
// 256x128x32 CTA tile, 3-stage cp.async, 256 threads: 8 warps 4(m) x 2(n),
// each warp 64x64 (4x8 m16n8k8), fragments double-buffered across ks.
#define ASTRIDE 36     // floats per A/Bn row (32 + 4 pad)
#define BSTRIDE 136    // floats per Bt row  (128 + 8 pad)
#define ABYTES  (256 * ASTRIDE * 4)   // 36864
#define BBYTES  18432                 // max(32*136, 128*36) * 4
#define STAGE   (ABYTES + BBYTES)     // 55296
#define NSTG    3

template <bool TRANSB, bool ACCUM, bool CAUSAL_QK, bool CAUSAL_PV, bool ROUND>
__global__ __launch_bounds__(256, 1)
void mma_gemm(const float* __restrict__ A, long long lda, long long strideA,
              const float* __restrict__ B, long long ldb, long long strideB,
              float* __restrict__ C, long long ldc, long long strideC,
              int K, float alpha)
{
    const int bx = blockIdx.x;   // m tile
    const int by = blockIdx.y;   // n tile
    const int bz = blockIdx.z;
    if (CAUSAL_QK && by > 2 * bx + 1) return;   // tile fully above diagonal

    A += (size_t)bz * strideA;
    B += (size_t)bz * strideB;
    C += (size_t)bz * strideC;

    const int m0 = bx * 256;
    const int n0 = by * 128;
    const int K_eff = CAUSAL_PV ? min(K, m0 + 256) : K;
    const int NT = K_eff >> 5;

    extern __shared__ char smem[];
    const uint32_t sm_u = smem_u32(smem);

    const int tid = threadIdx.x;
    const int lane = tid & 31;
    const int warp = tid >> 5;
    const int wm = warp & 3;          // 0..3  (64 rows each)
    const int wn = warp >> 2;         // 0..1  (64 cols each)
    const int g = lane >> 2;          // 0..7
    const int tig = lane & 3;         // 0..3

    // producer indices
    const int a_row = tid >> 3;       // 0..31
    const int a_c4  = tid & 7;

    float acc[4][8][4];
    #pragma unroll
    for (int i = 0; i < 4; i++)
        #pragma unroll
        for (int j = 0; j < 8; j++)
            #pragma unroll
            for (int r = 0; r < 4; r++) acc[i][j][r] = 0.f;

    auto load_stage = [&](int st, int t) {
        const uint32_t abase = sm_u + st * STAGE;
        const uint32_t bbase = abase + ABYTES;
        const long long kk = (long long)t << 5;
        // A tile: 256 rows x 32 floats, layout [m][k] stride 36
        #pragma unroll
        for (int i = 0; i < 8; i++) {
            int row = a_row + 32 * i;
            uint32_t so = abase + (uint32_t)(row * ASTRIDE + a_c4 * 4) * 4;
            const float* gp = A + (size_t)(m0 + row) * lda + kk + a_c4 * 4;
            CP_ASYNC16(so, gp);
        }
        if (TRANSB) {
            // B tile: 32 k-rows x 128 n, layout [k][n] stride 136
            #pragma unroll
            for (int i = 0; i < 4; i++) {
                int idx = tid + 256 * i;
                int kr = idx >> 5;           // 0..31
                int c4 = idx & 31;           // 0..31
                uint32_t so = bbase + (uint32_t)(kr * BSTRIDE + c4 * 4) * 4;
                const float* gp = B + (size_t)(kk + kr) * ldb + n0 + c4 * 4;
                CP_ASYNC16(so, gp);
            }
        } else {
            // B tile: 128 n-rows x 32 k, layout [n][k] stride 36
            #pragma unroll
            for (int i = 0; i < 4; i++) {
                int row = a_row + 32 * i;
                uint32_t so = bbase + (uint32_t)(row * ASTRIDE + a_c4 * 4) * 4;
                const float* gp = B + (size_t)(n0 + row) * ldb + kk + a_c4 * 4;
                CP_ASYNC16(so, gp);
            }
        }
    };

    // prefetch 2 stages
    #pragma unroll
    for (int s = 0; s < NSTG - 1; s++) {
        if (s < NT) load_stage(s, s);
        CP_COMMIT();
    }
    CP_WAIT1();
    __syncthreads();

    int st = 0;                        // stage of chunk t
    for (int t = 0; t < NT; t++) {
        int lt = t + NSTG - 1;
        int lst = st + NSTG - 1; if (lst >= NSTG) lst -= NSTG;
        if (lt < NT) load_stage(lst, lt);
        CP_COMMIT();

        const float* As = (const float*)(smem + st * STAGE);
        const float* Bs = (const float*)(smem + st * STAGE + ABYTES);

        const float* Abase = As + (wm * 64 + g) * ASTRIDE + tig;
        const float* Btb = Bs + tig * BSTRIDE + wn * 64 + g;   // TRANSB
        const float* Bnb = Bs + (wn * 64 + g) * ASTRIDE + tig; // !TRANSB

        // fragment double buffer across ks
        uint32_t af[2][4][4], bf[2][8][2];

        auto load_frag = [&](int ks, int buf) {
            #pragma unroll
            for (int mi = 0; mi < 4; mi++) {
                const float* p = Abase + ks * 8 + mi * (16 * ASTRIDE);
                af[buf][mi][0] = __float_as_uint(p[0]);
                af[buf][mi][1] = __float_as_uint(p[8 * ASTRIDE]);
                af[buf][mi][2] = __float_as_uint(p[4]);
                af[buf][mi][3] = __float_as_uint(p[8 * ASTRIDE + 4]);
            }
            if (TRANSB) {
                const float* p = Btb + ks * 8 * BSTRIDE;
                #pragma unroll
                for (int nj = 0; nj < 8; nj++) {
                    bf[buf][nj][0] = __float_as_uint(p[nj * 8]);
                    bf[buf][nj][1] = __float_as_uint(p[4 * BSTRIDE + nj * 8]);
                }
            } else {
                const float* p = Bnb + ks * 8;
                #pragma unroll
                for (int nj = 0; nj < 8; nj++) {
                    bf[buf][nj][0] = __float_as_uint(p[nj * 8 * ASTRIDE]);
                    bf[buf][nj][1] = __float_as_uint(p[nj * 8 * ASTRIDE + 4]);
                }
            }
        };

        load_frag(0, 0);
        #pragma unroll
        for (int ks = 0; ks < 4; ks++) {
            int cur = ks & 1;
            if (ks < 3) load_frag(ks + 1, cur ^ 1);
            #pragma unroll
            for (int mi = 0; mi < 4; mi++)
                #pragma unroll
                for (int nj = 0; nj < 8; nj++)
                    mma1688(acc[mi][nj], af[cur][mi], bf[cur][nj]);
        }
        CP_WAIT1();
        __syncthreads();
        if (++st == NSTG) st = 0;
    }

    // epilogue
    #pragma unroll
    for (int mi = 0; mi < 4; mi++) {
        #pragma unroll
        for (int nj = 0; nj < 8; nj++) {
            int row = m0 + wm * 64 + mi * 16 + g;
            int col = n0 + wn * 64 + nj * 8 + tig * 2;
            float2 v0, v1;
            v0.x = acc[mi][nj][0] * alpha; v0.y = acc[mi][nj][1] * alpha;
            v1.x = acc[mi][nj][2] * alpha; v1.y = acc[mi][nj][3] * alpha;
            if (ROUND) {
                v0.x = tf32r(v0.x); v0.y = tf32r(v0.y);
                v1.x = tf32r(v1.x); v1.y = tf32r(v1.y);
            }
            float2* p0 = (float2*)(C + (size_t)row * ldc + col);
            float2* p1 = (float2*)(C + (size_t)(row + 8) * ldc + col);
            if (ACCUM) {
                float2 o0 = *p0, o1 = *p1;
                v0.x += o0.x; v0.y += o0.y; v1.x += o1.x; v1.y += o1.y;
            }
            *p0 = v0;
            *p1 = v1;
        }
    }
}

// ------------------------ causal softmax (in place) -------------------------
// PV GEMM uses 256-row M tiles and reads k < m0+256; zero-fill to 256 boundary.
__global__ __launch_bounds__(256) void softmax_causal(void) {
    int i = blockIdx.x;       // query row
    int h = blockIdx.y;       // head
    float* row = g_sim + ((size_t)h * NSEQ + i) * NSEQ;
    float4* row4 = (float4*)row;
    int L = i + 1;
    int Lr = (L + 255) & ~255;
    int nv = L >> 2;          // full float4s
    int tid = threadIdx.x;

    __shared__ float red[256];

    float m = -INFINITY;
    for (int j = tid; j < nv; j += 256) {
        float4 v = row4[j];
        m = fmaxf(m, fmaxf(fmaxf(v.x, v.y), fmaxf(v.z, v.w)));
    }
    for (int j = (nv << 2) + tid; j < L; j += 256) m = fmaxf(m, row[j]);
    red[tid] = m;
    __syncthreads();
    for (int off = 128; off > 0; off >>= 1) {
        if (tid < off) red[tid] = fmaxf(red[tid], red[tid + off]);
        __syncthreads();
    }
    m = red[0];
    __syncthreads();

    float s = 0.f;
    for (int j = tid; j < nv; j += 256) {
        float4 v = row4[j];
        v.x = expf(v.x - m); v.y = expf(v.y - m);
        v.z = expf(v.z - m); v.w = expf(v.w - m);
        row4[j] = v;
        s += v.x + v.y + v.z + v.w;
    }
    for (int j = (nv << 2) + tid; j < L; j += 256) {
        float e = expf(row[j] - m);
        row[j] = e;
        s += e;
    }
    red[tid] = s;
    __syncthreads();
    for (int off = 128; off > 0; off >>= 1) {
        if (tid < off) red[tid] += red[tid + off];
        __syncthreads();
    }
    float inv = 1.0f / red[0];

    for (int j = tid; j < nv; j += 256) {
        float4 v = row4[j];
        v.x = tf32r(v.x * inv); v.y = tf32r(v.y * inv);
        v.z = tf32r(v.z * inv); v.w = tf32r(v.w * inv);
        row4[j] = v;
    }
    for (int j = (nv << 2) + tid; j < L; j += 256) row[j] = tf32r(row[j] * inv);
    for (int j = L + tid; j < Lr; j += 256) row[j] = 0.f;
}

// --------------------------- SwiGLU activation ------------------------------
// writes into concat buffer columns [2048, 10240)
__global__ __launch_bounds__(256) void ff_act_kernel(void) {
    int row = blockIdx.y;
    int j4 = blockIdx.x * 256 + threadIdx.x;       // 0..2047 (float4 index)
    const float* prow = g_proj + (size_t)row * FUSED_OUT;
    float4 xv = *(const float4*)(prow + FF_BASE + j4 * 4);
    float4 gg = *(const float4*)(prow + GATE_BASE + j4 * 4);
    float4 o;
    o.x = tf32r(xv.x * (gg.x / (1.0f + expf(-gg.x))));
    o.y = tf32r(xv.y * (gg.y / (1.0f + expf(-gg.y))));
    o.z = tf32r(xv.z * (gg.z / (1.0f + expf(-gg.z))));
    o.w = tf32r(xv.w * (gg.w / (1.0f + expf(-gg.w))));
    *(float4*)(g_cat + (size_t)row * CAT_K + ATTN_INNER + j4 * 4) = o;
}

// ------------------------------- launch -------------------------------------
extern "C" void kernel_launch(void* const* d_in, const int* in_sizes, int n_in,
                              void* d_out, int out_size) {
    const float* x          = (const float*)d_in[0];
    const float* gamma      = (const float*)d_in[1];
    const float* w_fused    = (const float*)d_in[2];
    const float* w_attn_out = (const float*)d_in[3];
    const float* w_ff_out   = (const float*)d_in[4];
    float* out = (float*)d_out;

    float *p_xn, *p_proj, *p_sim, *p_cat, *p_wf, *p_wcat;
    cudaGetSymbolAddress((void**)&p_xn, g_xn);
    cudaGetSymbolAddress((void**)&p_proj, g_proj);
    cudaGetSymbolAddress((void**)&p_sim, g_sim);
    cudaGetSymbolAddress((void**)&p_cat, g_cat);
    cudaGetSymbolAddress((void**)&p_wf, g_wf);
    cudaGetSymbolAddress((void**)&p_wcat, g_wcat);

    const int SMEM_DYN = NSTG * STAGE;   // 165888 B
    cudaFuncSetAttribute((const void*)mma_gemm<true,  false, false, false, true>,
                         cudaFuncAttributeMaxDynamicSharedMemorySize, SMEM_DYN);
    cudaFuncSetAttribute((const void*)mma_gemm<false, false, true,  false, false>,
                         cudaFuncAttributeMaxDynamicSharedMemorySize, SMEM_DYN);
    cudaFuncSetAttribute((const void*)mma_gemm<true,  false, false, true,  true>,
                         cudaFuncAttributeMaxDynamicSharedMemorySize, SMEM_DYN);
    cudaFuncSetAttribute((const void*)mma_gemm<true,  false, false, false, false>,
                         cudaFuncAttributeMaxDynamicSharedMemorySize, SMEM_DYN);

    const float scale = 0.08838834764831845f;  // 128^-0.5

    // 0. round weights to tf32 (RNA); stack output weights into one [10240 x 2048]
    round_kernel<<<2048, 256>>>((const float4*)w_fused, (float4*)p_wf,
                                (size_t)DIM * FUSED_OUT / 4);
    round_kernel<<<1024, 256>>>((const float4*)w_attn_out, (float4*)p_wcat,
                                (size_t)ATTN_INNER * DIM / 4);
    round_kernel<<<1024, 256>>>((const float4*)w_ff_out,
                                (float4*)(p_wcat + (size_t)ATTN_INNER * DIM),
                                (size_t)FF_INNER * DIM / 4);

    // 1. LayerNorm (tf32-rounded output)
    ln_kernel<<<NSEQ, 256>>>(x, gamma);

    // 2. proj = xn @ w_fused  [2048x2048]x[2048x18688]
    mma_gemm<true, false, false, false, true>
        <<<dim3(NSEQ / 256, FUSED_OUT / 128, 1), 256, SMEM_DYN>>>(
        p_xn, DIM, 0, p_wf, FUSED_OUT, 0, p_proj, FUSED_OUT, 0, DIM, 1.0f);

    // 3. sim_h = scale * Q_h @ K^T  (K matrix [N,dh] k-contiguous -> !TRANSB)
    mma_gemm<false, false, true, false, false>
        <<<dim3(NSEQ / 256, NSEQ / 128, HEADS), 256, SMEM_DYN>>>(
        p_proj, FUSED_OUT, DH,
        p_proj + ATTN_INNER, FUSED_OUT, 0,
        p_sim, NSEQ, (long long)NSEQ * NSEQ, DH, scale);

    // 4. causal softmax (zero-fill to 256 boundary)
    softmax_causal<<<dim3(NSEQ, HEADS), 256>>>();

    // 5. attn_h = P_h @ V -> concat buffer cols [0,2048)  (TRANSB, K clipped)
    mma_gemm<true, false, false, true, true>
        <<<dim3(NSEQ / 256, 1, HEADS), 256, SMEM_DYN>>>(
        p_sim, NSEQ, (long long)NSEQ * NSEQ,
        p_proj + ATTN_INNER + DH, FUSED_OUT, 0,
        p_cat, CAT_K, DH, NSEQ, 1.0f);

    // 6. SwiGLU -> concat buffer cols [2048, 10240)
    ff_act_kernel<<<dim3(FF_INNER / 1024, NSEQ), 256>>>();

    // 7. out = cat @ wcat   [2048x10240]x[10240x2048]  (replaces old 7+8)
    mma_gemm<true, false, false, false, false>
        <<<dim3(NSEQ / 256, DIM / 128, 1), 256, SMEM_DYN>>>(
        p_cat, CAT_K, 0, p_wcat, DIM, 0, out, DIM, 0, CAT_K, 1.0f);
}

// round 8
// speedup vs baseline: 1.5247x; 1.5247x over previous
#include <cuda_runtime.h>
#include <cuda_bf16.h>
#include <cstdint>
#include <math.h>

// ---------------------------------------------------------------------------
// ParallelTransformerBlock via legacy tensor-core path (mma.sync tf32 + cp.async)
// B=1, N=2048, DIM=2048, HEADS=16, DH=128, FF_INNER=8192, FUSED_OUT=18688
// R8: R6 mainloop (single fragment buffer, no spills) + merged output GEMM.
// ---------------------------------------------------------------------------

#define NSEQ 2048
#define DIM 2048
#define DH 128
#define HEADS 16
#define ATTN_INNER 2048
#define FF_INNER 8192
#define FUSED_OUT 18688
#define FF_BASE 2304      // ATTN_INNER + 2*DH
#define GATE_BASE 10496   // FF_BASE + FF_INNER
#define CAT_K (ATTN_INNER + FF_INNER)   // 10240
#define LN_EPS 1e-5f

// ------------------------- device scratch (static) -------------------------
__device__ float g_xn[(size_t)NSEQ * DIM];                    // 16 MB
__device__ float g_proj[(size_t)NSEQ * FUSED_OUT];            // 153 MB
__device__ float g_sim[(size_t)HEADS * NSEQ * NSEQ];          // 256 MB
__device__ float g_cat[(size_t)NSEQ * CAT_K];                 // 80 MB (attnc | ffact)
// tf32-rounded weight copies
__device__ float g_wf[(size_t)DIM * FUSED_OUT];               // 153 MB
__device__ float g_wcat[(size_t)CAT_K * DIM];                 // 80 MB (wao ; wfo stacked)

// --------------------------- PTX helpers -----------------------------------
__device__ __forceinline__ uint32_t smem_u32(const void* p) {
    uint32_t a;
    asm("{ .reg .u64 t; cvta.to.shared.u64 t, %1; cvt.u32.u64 %0, t; }"
        : "=r"(a) : "l"(p));
    return a;
}

__device__ __forceinline__ float tf32r(float x) {
    uint32_t u;
    asm("cvt.rna.tf32.f32 %0, %1;" : "=r"(u) : "f"(x));
    return __uint_as_float(u);
}

#define CP_ASYNC16(smaddr, gptr) \
    asm volatile("cp.async.cg.shared.global [%0], [%1], 16;" :: "r"(smaddr), "l"(gptr))
#define CP_COMMIT() asm volatile("cp.async.commit_group;" ::: "memory")
#define CP_WAIT1()  asm volatile("cp.async.wait_group 1;" ::: "memory")

__device__ __forceinline__ void mma1688(float* d, const uint32_t* a, const uint32_t* b) {
    asm volatile(
        "mma.sync.aligned.m16n8k8.row.col.f32.tf32.tf32.f32 "
        "{%0,%1,%2,%3}, {%4,%5,%6,%7}, {%8,%9}, {%0,%1,%2,%3};"
        : "+f"(d[0]), "+f"(d[1]), "+f"(d[2]), "+f"(d[3])
        : "r"(a[0]), "r"(a[1]), "r"(a[2]), "r"(a[3]), "r"(b[0]), "r"(b[1]));
}

// ------------------------------ LayerNorm ----------------------------------
__global__ __launch_bounds__(256) void ln_kernel(const float* __restrict__ x,
                                                 const float* __restrict__ gamma) {
    int row = blockIdx.x;
    int tid = threadIdx.x;
    const float4* xr = (const float4*)(x + (size_t)row * DIM);
    float4* out = (float4*)(g_xn + (size_t)row * DIM);
    const float4* g4 = (const float4*)gamma;

    float s = 0.f, sq = 0.f;
    float4 v[2];
    #pragma unroll
    for (int i = 0; i < 2; i++) {
        v[i] = xr[tid + 256 * i];
        s += v[i].x + v[i].y + v[i].z + v[i].w;
        sq += v[i].x * v[i].x + v[i].y * v[i].y + v[i].z * v[i].z + v[i].w * v[i].w;
    }
    __shared__ float red[256], red2[256];
    red[tid] = s; red2[tid] = sq;
    __syncthreads();
    for (int off = 128; off > 0; off >>= 1) {
        if (tid < off) { red[tid] += red[tid + off]; red2[tid] += red2[tid + off]; }
        __syncthreads();
    }
    float mu = red[0] * (1.0f / DIM);
    float var = red2[0] * (1.0f / DIM) - mu * mu;
    float inv = rsqrtf(var + LN_EPS);
    #pragma unroll
    for (int i = 0; i < 2; i++) {
        float4 g = g4[tid + 256 * i];
        float4 o;
        o.x = tf32r((v[i].x - mu) * inv * g.x);
        o.y = tf32r((v[i].y - mu) * inv * g.y);
        o.z = tf32r((v[i].z - mu) * inv * g.z);
        o.w = tf32r((v[i].w - mu) * inv * g.w);
        out[tid + 256 * i] = o;
    }
}

// ------------------------- weight rounding (tf32) ---------------------------
__global__ __launch_bounds__(256) void round_kernel(const float4* __restrict__ src,
                                                    float4* __restrict__ dst, size_t n4) {
    for (size_t i = (size_t)blockIdx.x * 256 + threadIdx.x; i < n4;
         i += (size_t)gridDim.x * 256) {
        float4 v = src[i];
        v.x = tf32r(v.x); v.y = tf32r(v.y); v.z = tf32r(v.z); v.w = tf32r(v.w);
        dst[i] = v;
    }
}

// ------------------------- tensor-core tf32 GEMM ----------------------------
// C[M,N] (+)= alpha * A[M,K] @ B.
//  TRANSB=false: B stored [N,K] row-major (k contiguous)  -> Bs[n][k]
//  TRANSB=true : B stored [K,N] row-major (n contiguous)  -> Bs[k][n]
// blockIdx.x = M tile (256 rows), blockIdx.y = N tile (128 cols), z = batch.
// 256x128x32 CTA tile, 3-stage cp.async, 256 threads: 8 warps 4(m) x 2(n),
// each warp 64x64 (4x8 m16n8k8 fragments). Single fragment buffer (no spill).
#define ASTRIDE 36     // floats per A/Bn row (32 + 4 pad)
#define BSTRIDE 136    // floats per Bt row  (128 + 8 pad)
#define ABYTES  (256 * ASTRIDE * 4)   // 36864
#define BBYTES  18432                 // max(32*136, 128*36) * 4
#define STAGE   (ABYTES + BBYTES)     // 55296
#define NSTG    3

template <bool TRANSB, bool ACCUM, bool CAUSAL_QK, bool CAUSAL_PV, bool ROUND>
__global__ __launch_bounds__(256, 1)
void mma_gemm(const float* __restrict__ A, long long lda, long long strideA,
              const float* __restrict__ B, long long ldb, long long strideB,
              float* __restrict__ C, long long ldc, long long strideC,
              int K, float alpha)
{
    const int bx = blockIdx.x;   // m tile
    const int by = blockIdx.y;   // n tile
    const int bz = blockIdx.z;
    if (CAUSAL_QK && by > 2 * bx + 1) return;   // tile fully above diagonal

    A += (size_t)bz * strideA;
    B += (size_t)bz * strideB;
    C += (size_t)bz * strideC;

    const int m0 = bx * 256;
    const int n0 = by * 128;
    const int K_eff = CAUSAL_PV ? min(K, m0 + 256) : K;
    const int NT = K_eff >> 5;

    extern __shared__ char smem[];
    const uint32_t sm_u = smem_u32(smem);

    const int tid = threadIdx.x;
    const int lane = tid & 31;
    const int warp = tid >> 5;
    const int wm = warp & 3;          // 0..3  (64 rows each)
    const int wn = warp >> 2;         // 0..1  (64 cols each)
    const int g = lane >> 2;          // 0..7
    const int tig = lane & 3;         // 0..3

    // producer indices
    const int a_row = tid >> 3;       // 0..31
    const int a_c4  = tid & 7;

    float acc[4][8][4];
    #pragma unroll
    for (int i = 0; i < 4; i++)
        #pragma unroll
        for (int j = 0; j < 8; j++)
            #pragma unroll
            for (int r = 0; r < 4; r++) acc[i][j][r] = 0.f;

    auto load_stage = [&](int st, int t) {
        const uint32_t abase = sm_u + st * STAGE;
        const uint32_t bbase = abase + ABYTES;
        const long long kk = (long long)t << 5;
        // A tile: 256 rows x 32 floats, layout [m][k] stride 36
        #pragma unroll
        for (int i = 0; i < 8; i++) {
            int row = a_row + 32 * i;
            uint32_t so = abase + (uint32_t)(row * ASTRIDE + a_c4 * 4) * 4;
            const float* gp = A + (size_t)(m0 + row) * lda + kk + a_c4 * 4;
            CP_ASYNC16(so, gp);
        }
        if (TRANSB) {
            // B tile: 32 k-rows x 128 n, layout [k][n] stride 136
            #pragma unroll
            for (int i = 0; i < 4; i++) {
                int idx = tid + 256 * i;
                int kr = idx >> 5;           // 0..31
                int c4 = idx & 31;           // 0..31
                uint32_t so = bbase + (uint32_t)(kr * BSTRIDE + c4 * 4) * 4;
                const float* gp = B + (size_t)(kk + kr) * ldb + n0 + c4 * 4;
                CP_ASYNC16(so, gp);
            }
        } else {
            // B tile: 128 n-rows x 32 k, layout [n][k] stride 36
            #pragma unroll
            for (int i = 0; i < 4; i++) {
                int row = a_row + 32 * i;
                uint32_t so = bbase + (uint32_t)(row * ASTRIDE + a_c4 * 4) * 4;
                const float* gp = B + (size_t)(n0 + row) * ldb + kk + a_c4 * 4;
                CP_ASYNC16(so, gp);
            }
        }
    };

    // prefetch 2 stages
    #pragma unroll
    for (int s = 0; s < NSTG - 1; s++) {
        if (s < NT) load_stage(s, s);
        CP_COMMIT();
    }
    CP_WAIT1();
    __syncthreads();

    int st = 0;                        // stage of chunk t
    for (int t = 0; t < NT; t++) {
        int lt = t + NSTG - 1;
        int lst = st + NSTG - 1; if (lst >= NSTG) lst -= NSTG;
        if (lt < NT) load_stage(lst, lt);
        CP_COMMIT();

        const float* As = (const float*)(smem + st * STAGE);
        const float* Bs = (const float*)(smem + st * STAGE + ABYTES);

        const float* Abase = As + (wm * 64 + g) * ASTRIDE + tig;
        const float* Btb = Bs + tig * BSTRIDE + wn * 64 + g;   // TRANSB
        const float* Bnb = Bs + (wn * 64 + g) * ASTRIDE + tig; // !TRANSB

        #pragma unroll
        for (int ks = 0; ks < 4; ks++) {
            uint32_t af[4][4], bf[8][2];
            #pragma unroll
            for (int mi = 0; mi < 4; mi++) {
                const float* p = Abase + ks * 8 + mi * (16 * ASTRIDE);
                af[mi][0] = __float_as_uint(p[0]);
                af[mi][1] = __float_as_uint(p[8 * ASTRIDE]);
                af[mi][2] = __float_as_uint(p[4]);
                af[mi][3] = __float_as_uint(p[8 * ASTRIDE + 4]);
            }
            if (TRANSB) {
                const float* p = Btb + ks * 8 * BSTRIDE;
                #pragma unroll
                for (int nj = 0; nj < 8; nj++) {
                    bf[nj][0] = __float_as_uint(p[nj * 8]);
                    bf[nj][1] = __float_as_uint(p[4 * BSTRIDE + nj * 8]);
                }
            } else {
                const float* p = Bnb + ks * 8;
                #pragma unroll
                for (int nj = 0; nj < 8; nj++) {
                    bf[nj][0] = __float_as_uint(p[nj * 8 * ASTRIDE]);
                    bf[nj][1] = __float_as_uint(p[nj * 8 * ASTRIDE + 4]);
                }
            }
            #pragma unroll
            for (int mi = 0; mi < 4; mi++)
                #pragma unroll
                for (int nj = 0; nj < 8; nj++)
                    mma1688(acc[mi][nj], af[mi], bf[nj]);
        }
        CP_WAIT1();
        __syncthreads();
        if (++st == NSTG) st = 0;
    }

    // epilogue
    #pragma unroll
    for (int mi = 0; mi < 4; mi++) {
        #pragma unroll
        for (int nj = 0; nj < 8; nj++) {
            int row = m0 + wm * 64 + mi * 16 + g;
            int col = n0 + wn * 64 + nj * 8 + tig * 2;
            float2 v0, v1;
            v0.x = acc[mi][nj][0] * alpha; v0.y = acc[mi][nj][1] * alpha;
            v1.x = acc[mi][nj][2] * alpha; v1.y = acc[mi][nj][3] * alpha;
            if (ROUND) {
                v0.x = tf32r(v0.x); v0.y = tf32r(v0.y);
                v1.x = tf32r(v1.x); v1.y = tf32r(v1.y);
            }
            float2* p0 = (float2*)(C + (size_t)row * ldc + col);
            float2* p1 = (float2*)(C + (size_t)(row + 8) * ldc + col);
            if (ACCUM) {
                float2 o0 = *p0, o1 = *p1;
                v0.x += o0.x; v0.y += o0.y; v1.x += o1.x; v1.y += o1.y;
            }
            *p0 = v0;
            *p1 = v1;
        }
    }
}

// ------------------------ causal softmax (in place) -------------------------
// PV GEMM uses 256-row M tiles and reads k < m0+256; zero-fill to 256 boundary.
__global__ __launch_bounds__(256) void softmax_causal(void) {
    int i = blockIdx.x;       // query row
    int h = blockIdx.y;       // head
    float* row = g_sim + ((size_t)h * NSEQ + i) * NSEQ;
    float4* row4 = (float4*)row;
    int L = i + 1;
    int Lr = (L + 255) & ~255;
    int nv = L >> 2;          // full float4s
    int tid = threadIdx.x;

    __shared__ float red[256];

    float m = -INFINITY;
    for (int j = tid; j < nv; j += 256) {
        float4 v = row4[j];
        m = fmaxf(m, fmaxf(fmaxf(v.x, v.y), fmaxf(v.z, v.w)));
    }
    for (int j = (nv << 2) + tid; j < L; j += 256) m = fmaxf(m, row[j]);
    red[tid] = m;
    __syncthreads();
    for (int off = 128; off > 0; off >>= 1) {
        if (tid < off) red[tid] = fmaxf(red[tid], red[tid + off]);
        __syncthreads();
    }
    m = red[0];
    __syncthreads();

    float s = 0.f;
    for (int j = tid; j < nv; j += 256) {
        float4 v = row4[j];
        v.x = expf(v.x - m); v.y = expf(v.y - m);
        v.z = expf(v.z - m); v.w = expf(v.w - m);
        row4[j] = v;
        s += v.x + v.y + v.z + v.w;
    }
    for (int j = (nv << 2) + tid; j < L; j += 256) {
        float e = expf(row[j] - m);
        row[j] = e;
        s += e;
    }
    red[tid] = s;
    __syncthreads();
    for (int off = 128; off > 0; off >>= 1) {
        if (tid < off) red[tid] += red[tid + off];
        __syncthreads();
    }
    float inv = 1.0f / red[0];

    for (int j = tid; j < nv; j += 256) {
        float4 v = row4[j];
        v.x = tf32r(v.x * inv); v.y = tf32r(v.y * inv);
        v.z = tf32r(v.z * inv); v.w = tf32r(v.w * inv);
        row4[j] = v;
    }
    for (int j = (nv << 2) + tid; j < L; j += 256) row[j] = tf32r(row[j] * inv);
    for (int j = L + tid; j < Lr; j += 256) row[j] = 0.f;
}

// --------------------------- SwiGLU activation ------------------------------
// writes into concat buffer columns [2048, 10240)
__global__ __launch_bounds__(256) void ff_act_kernel(void) {
    int row = blockIdx.y;
    int j4 = blockIdx.x * 256 + threadIdx.x;       // 0..2047 (float4 index)
    const float* prow = g_proj + (size_t)row * FUSED_OUT;
    float4 xv = *(const float4*)(prow + FF_BASE + j4 * 4);
    float4 gg = *(const float4*)(prow + GATE_BASE + j4 * 4);
    float4 o;
    o.x = tf32r(xv.x * (gg.x / (1.0f + expf(-gg.x))));
    o.y = tf32r(xv.y * (gg.y / (1.0f + expf(-gg.y))));
    o.z = tf32r(xv.z * (gg.z / (1.0f + expf(-gg.z))));
    o.w = tf32r(xv.w * (gg.w / (1.0f + expf(-gg.w))));
    *(float4*)(g_cat + (size_t)row * CAT_K + ATTN_INNER + j4 * 4) = o;
}

// ------------------------------- launch -------------------------------------
extern "C" void kernel_launch(void* const* d_in, const int* in_sizes, int n_in,
                              void* d_out, int out_size) {
    const float* x          = (const float*)d_in[0];
    const float* gamma      = (const float*)d_in[1];
    const float* w_fused    = (const float*)d_in[2];
    const float* w_attn_out = (const float*)d_in[3];
    const float* w_ff_out   = (const float*)d_in[4];
    float* out = (float*)d_out;

    float *p_xn, *p_proj, *p_sim, *p_cat, *p_wf, *p_wcat;
    cudaGetSymbolAddress((void**)&p_xn, g_xn);
    cudaGetSymbolAddress((void**)&p_proj, g_proj);
    cudaGetSymbolAddress((void**)&p_sim, g_sim);
    cudaGetSymbolAddress((void**)&p_cat, g_cat);
    cudaGetSymbolAddress((void**)&p_wf, g_wf);
    cudaGetSymbolAddress((void**)&p_wcat, g_wcat);

    const int SMEM_DYN = NSTG * STAGE;   // 165888 B
    cudaFuncSetAttribute((const void*)mma_gemm<true,  false, false, false, true>,
                         cudaFuncAttributeMaxDynamicSharedMemorySize, SMEM_DYN);
    cudaFuncSetAttribute((const void*)mma_gemm<false, false, true,  false, false>,
                         cudaFuncAttributeMaxDynamicSharedMemorySize, SMEM_DYN);
    cudaFuncSetAttribute((const void*)mma_gemm<true,  false, false, true,  true>,
                         cudaFuncAttributeMaxDynamicSharedMemorySize, SMEM_DYN);
    cudaFuncSetAttribute((const void*)mma_gemm<true,  false, false, false, false>,
                         cudaFuncAttributeMaxDynamicSharedMemorySize, SMEM_DYN);

    const float scale = 0.08838834764831845f;  // 128^-0.5

    // 0. round weights to tf32 (RNA); stack output weights into one [10240 x 2048]
    round_kernel<<<2048, 256>>>((const float4*)w_fused, (float4*)p_wf,
                                (size_t)DIM * FUSED_OUT / 4);
    round_kernel<<<1024, 256>>>((const float4*)w_attn_out, (float4*)p_wcat,
                                (size_t)ATTN_INNER * DIM / 4);
    round_kernel<<<1024, 256>>>((const float4*)w_ff_out,
                                (float4*)(p_wcat + (size_t)ATTN_INNER * DIM),
                                (size_t)FF_INNER * DIM / 4);

    // 1. LayerNorm (tf32-rounded output)
    ln_kernel<<<NSEQ, 256>>>(x, gamma);

    // 2. proj = xn @ w_fused  [2048x2048]x[2048x18688]
    mma_gemm<true, false, false, false, true>
        <<<dim3(NSEQ / 256, FUSED_OUT / 128, 1), 256, SMEM_DYN>>>(
        p_xn, DIM, 0, p_wf, FUSED_OUT, 0, p_proj, FUSED_OUT, 0, DIM, 1.0f);

    // 3. sim_h = scale * Q_h @ K^T  (K matrix [N,dh] k-contiguous -> !TRANSB)
    mma_gemm<false, false, true, false, false>
        <<<dim3(NSEQ / 256, NSEQ / 128, HEADS), 256, SMEM_DYN>>>(
        p_proj, FUSED_OUT, DH,
        p_proj + ATTN_INNER, FUSED_OUT, 0,
        p_sim, NSEQ, (long long)NSEQ * NSEQ, DH, scale);

    // 4. causal softmax (zero-fill to 256 boundary)
    softmax_causal<<<dim3(NSEQ, HEADS), 256>>>();

    // 5. attn_h = P_h @ V -> concat buffer cols [0,2048)  (TRANSB, K clipped)
    mma_gemm<true, false, false, true, true>
        <<<dim3(NSEQ / 256, 1, HEADS), 256, SMEM_DYN>>>(
        p_sim, NSEQ, (long long)NSEQ * NSEQ,
        p_proj + ATTN_INNER + DH, FUSED_OUT, 0,
        p_cat, CAT_K, DH, NSEQ, 1.0f);

    // 6. SwiGLU -> concat buffer cols [2048, 10240)
    ff_act_kernel<<<dim3(FF_INNER / 1024, NSEQ), 256>>>();

    // 7. out = cat @ wcat   [2048x10240]x[10240x2048]  (merged old 7+8)
    mma_gemm<true, false, false, false, false>
        <<<dim3(NSEQ / 256, DIM / 128, 1), 256, SMEM_DYN>>>(
        p_cat, CAT_K, 0, p_wcat, DIM, 0, out, DIM, 0, CAT_K, 1.0f);
}

// round 9
// speedup vs baseline: 2.5426x; 1.6676x over previous
#include <cuda_runtime.h>
#include <cuda_fp16.h>
#include <cstdint>
#include <math.h>

// ---------------------------------------------------------------------------
// ParallelTransformerBlock, fp16 tensor-core path (mma.sync m16n8k16 + ldmatrix
// + cp.async). fp32 accumulate everywhere; sim kept fp32; operands fp16
// (same 10-bit mantissa as tf32 => same quantization error, 2x throughput).
// R9: all GEMMs share one !TRANSB kernel; weights pre-transposed to [N][K] half.
// ---------------------------------------------------------------------------

#define NSEQ 2048
#define DIM 2048
#define DH 128
#define HEADS 16
#define ATTN_INNER 2048
#define FF_INNER 8192
#define FUSED_OUT 18688
#define FF_BASE 2304      // ATTN_INNER + 2*DH
#define GATE_BASE 10496   // FF_BASE + FF_INNER
#define CAT_K (ATTN_INNER + FF_INNER)   // 10240
#define LN_EPS 1e-5f

// ------------------------- device scratch (static) -------------------------
__device__ __half g_xnh[(size_t)NSEQ * DIM];                    // 8 MB
__device__ __half g_projh[(size_t)NSEQ * FUSED_OUT];            // 76.5 MB
__device__ float  g_sim[(size_t)HEADS * NSEQ * NSEQ];           // 256 MB
__device__ __half g_p[(size_t)HEADS * NSEQ * NSEQ];             // 128 MB
__device__ __half g_cath[(size_t)NSEQ * CAT_K];                 // 40 MB
__device__ __half g_vt[(size_t)DH * NSEQ];                      // 0.5 MB
__device__ __half g_wft[(size_t)FUSED_OUT * DIM];               // 76.5 MB  [N][K]
__device__ __half g_wcatt[(size_t)DIM * CAT_K];                 // 40 MB    [2048][10240]

// --------------------------- PTX helpers -----------------------------------
__device__ __forceinline__ uint32_t smem_u32(const void* p) {
    uint32_t a;
    asm("{ .reg .u64 t; cvta.to.shared.u64 t, %1; cvt.u32.u64 %0, t; }"
        : "=r"(a) : "l"(p));
    return a;
}

#define CP_ASYNC16(smaddr, gptr) \
    asm volatile("cp.async.cg.shared.global [%0], [%1], 16;" :: "r"(smaddr), "l"(gptr))
#define CP_COMMIT() asm volatile("cp.async.commit_group;" ::: "memory")
#define CP_WAIT1()  asm volatile("cp.async.wait_group 1;" ::: "memory")

#define LDSM4(r, addr) \
    asm volatile("ldmatrix.sync.aligned.m8n8.x4.shared.b16 {%0,%1,%2,%3}, [%4];" \
                 : "=r"((r)[0]), "=r"((r)[1]), "=r"((r)[2]), "=r"((r)[3]) \
                 : "r"(addr))

__device__ __forceinline__ void mma16816(float* d, const uint32_t* a, const uint32_t* b) {
    asm volatile(
        "mma.sync.aligned.m16n8k16.row.col.f32.f16.f16.f32 "
        "{%0,%1,%2,%3}, {%4,%5,%6,%7}, {%8,%9}, {%0,%1,%2,%3};"
        : "+f"(d[0]), "+f"(d[1]), "+f"(d[2]), "+f"(d[3])
        : "r"(a[0]), "r"(a[1]), "r"(a[2]), "r"(a[3]), "r"(b[0]), "r"(b[1]));
}

// ------------------------------ LayerNorm ----------------------------------
__global__ __launch_bounds__(256) void ln_kernel(const float* __restrict__ x,
                                                 const float* __restrict__ gamma) {
    int row = blockIdx.x;
    int tid = threadIdx.x;
    const float4* xr = (const float4*)(x + (size_t)row * DIM);
    __half2* out = (__half2*)(g_xnh + (size_t)row * DIM);
    const float4* g4 = (const float4*)gamma;

    float s = 0.f, sq = 0.f;
    float4 v[2];
    #pragma unroll
    for (int i = 0; i < 2; i++) {
        v[i] = xr[tid + 256 * i];
        s += v[i].x + v[i].y + v[i].z + v[i].w;
        sq += v[i].x * v[i].x + v[i].y * v[i].y + v[i].z * v[i].z + v[i].w * v[i].w;
    }
    __shared__ float red[256], red2[256];
    red[tid] = s; red2[tid] = sq;
    __syncthreads();
    for (int off = 128; off > 0; off >>= 1) {
        if (tid < off) { red[tid] += red[tid + off]; red2[tid] += red2[tid + off]; }
        __syncthreads();
    }
    float mu = red[0] * (1.0f / DIM);
    float var = red2[0] * (1.0f / DIM) - mu * mu;
    float inv = rsqrtf(var + LN_EPS);
    #pragma unroll
    for (int i = 0; i < 2; i++) {
        float4 g = g4[tid + 256 * i];
        float a0 = (v[i].x - mu) * inv * g.x;
        float a1 = (v[i].y - mu) * inv * g.y;
        float a2 = (v[i].z - mu) * inv * g.z;
        float a3 = (v[i].w - mu) * inv * g.w;
        out[(tid + 256 * i) * 2 + 0] = __floats2half2_rn(a0, a1);
        out[(tid + 256 * i) * 2 + 1] = __floats2half2_rn(a2, a3);
    }
}

// --------------- weight transpose + fp16 convert: [K,N] -> [N,K] ------------
__global__ __launch_bounds__(256) void wtrans_kernel(const float* __restrict__ src,
                                                     int N, __half* __restrict__ dst,
                                                     long long ldd, long long koff) {
    __shared__ float tile[32][33];
    int n0 = blockIdx.x * 32;
    int k0 = blockIdx.y * 32;
    int tx = threadIdx.x & 31, ty = threadIdx.x >> 5;   // 32 x 8
    #pragma unroll
    for (int i = 0; i < 4; i++)
        tile[ty + 8 * i][tx] = src[(size_t)(k0 + ty + 8 * i) * N + n0 + tx];
    __syncthreads();
    #pragma unroll
    for (int i = 0; i < 4; i++)
        dst[(size_t)(n0 + ty + 8 * i) * ldd + koff + k0 + tx] =
            __float2half_rn(tile[tx][ty + 8 * i]);
}

// ---------------- V transpose (half->half): proj cols -> [DH][NSEQ] ---------
__global__ __launch_bounds__(256) void vtrans_kernel(void) {
    __shared__ __half tile[32][33];
    int s0 = blockIdx.x * 32;
    int d0 = blockIdx.y * 32;
    int tx = threadIdx.x & 31, ty = threadIdx.x >> 5;
    #pragma unroll
    for (int i = 0; i < 4; i++)
        tile[ty + 8 * i][tx] =
            g_projh[(size_t)(s0 + ty + 8 * i) * FUSED_OUT + ATTN_INNER + DH + d0 + tx];
    __syncthreads();
    #pragma unroll
    for (int i = 0; i < 4; i++)
        g_vt[(size_t)(d0 + ty + 8 * i) * NSEQ + s0 + tx] = tile[tx][ty + 8 * i];
}

// ------------------------- fp16 tensor-core GEMM ----------------------------
// C[M,N] = alpha * A[M,K] @ B^T, A half [M][K] k-contig, B half [N][K] k-contig.
// blockIdx.x = M tile (256), blockIdx.y = N tile (128), z = batch.
// 256x128x64 CTA tile, 3-stage cp.async, 256 threads: 8 warps 4(m) x 2(n),
// each warp 64x64 (4x8 m16n8k16), fragments via ldmatrix.x4.
#define ROWB   144                      // bytes per smem row (64 halves + 8 pad)
#define ABYTES (256 * ROWB)             // 36864
#define BBYTES (128 * ROWB)             // 18432
#define STAGE  (ABYTES + BBYTES)        // 55296
#define NSTG   3

template <bool CHALF, bool CAUSAL_QK, bool CAUSAL_PV>
__global__ __launch_bounds__(256, 1)
void mma_gemm(const __half* __restrict__ A, long long lda, long long strideA,
              const __half* __restrict__ B, long long ldb, long long strideB,
              void* __restrict__ Cv, long long ldc, long long strideC,
              int K, float alpha)
{
    const int bx = blockIdx.x;   // m tile
    const int by = blockIdx.y;   // n tile
    const int bz = blockIdx.z;
    if (CAUSAL_QK && by > 2 * bx + 1) return;   // tile fully above diagonal

    A += (size_t)bz * strideA;
    B += (size_t)bz * strideB;

    const int m0 = bx * 256;
    const int n0 = by * 128;
    const int K_eff = CAUSAL_PV ? min(K, m0 + 256) : K;
    const int NT = K_eff >> 6;                  // 64-wide K chunks

    extern __shared__ char smem[];
    const uint32_t sm_u = smem_u32(smem);

    const int tid = threadIdx.x;
    const int lane = tid & 31;
    const int warp = tid >> 5;
    const int wm = warp & 3;          // 0..3  (64 rows each)
    const int wn = warp >> 2;         // 0..1  (64 cols each)
    const int g = lane >> 2;          // 0..7
    const int tig = lane & 3;         // 0..3

    // ldmatrix per-lane byte offsets within a stage
    const uint32_t a_off = (uint32_t)((wm * 64 + (lane & 15)) * ROWB + ((lane >> 4) << 4));
    const uint32_t b_off = (uint32_t)(ABYTES +
        (wn * 64 + (lane & 7) + ((lane >> 4) << 3)) * ROWB + (((lane >> 3) & 1) << 4));

    float acc[4][8][4];
    #pragma unroll
    for (int i = 0; i < 4; i++)
        #pragma unroll
        for (int j = 0; j < 8; j++)
            #pragma unroll
            for (int r = 0; r < 4; r++) acc[i][j][r] = 0.f;

    auto load_stage = [&](int st, int t) {
        const uint32_t abase = sm_u + st * STAGE;
        const uint32_t bbase = abase + ABYTES;
        const long long kk = (long long)t << 6;
        #pragma unroll
        for (int i = 0; i < 8; i++) {              // A: 256 rows x 128B
            int idx = tid + 256 * i;
            int row = idx >> 3, seg = idx & 7;
            uint32_t so = abase + (uint32_t)(row * ROWB + seg * 16);
            const __half* gp = A + (size_t)(m0 + row) * lda + kk + seg * 8;
            CP_ASYNC16(so, gp);
        }
        #pragma unroll
        for (int i = 0; i < 4; i++) {              // B: 128 rows x 128B
            int idx = tid + 256 * i;
            int row = idx >> 3, seg = idx & 7;
            uint32_t so = bbase + (uint32_t)(row * ROWB + seg * 16);
            const __half* gp = B + (size_t)(n0 + row) * ldb + kk + seg * 8;
            CP_ASYNC16(so, gp);
        }
    };

    #pragma unroll
    for (int s = 0; s < NSTG - 1; s++) {
        if (s < NT) load_stage(s, s);
        CP_COMMIT();
    }
    CP_WAIT1();
    __syncthreads();

    int st = 0;
    for (int t = 0; t < NT; t++) {
        int lt = t + NSTG - 1;
        int lst = st + NSTG - 1; if (lst >= NSTG) lst -= NSTG;
        if (lt < NT) load_stage(lst, lt);
        CP_COMMIT();

        const uint32_t abase = sm_u + st * STAGE;

        #pragma unroll
        for (int ks = 0; ks < 4; ks++) {           // 4 x k16 steps
            uint32_t af[4][4], bf[4][4];
            #pragma unroll
            for (int mi = 0; mi < 4; mi++)
                LDSM4(af[mi], abase + a_off + mi * (16 * ROWB) + ks * 32);
            #pragma unroll
            for (int njp = 0; njp < 4; njp++)
                LDSM4(bf[njp], abase + b_off + njp * (16 * ROWB) + ks * 32);
            #pragma unroll
            for (int mi = 0; mi < 4; mi++)
                #pragma unroll
                for (int njp = 0; njp < 4; njp++) {
                    mma16816(acc[mi][2 * njp + 0], af[mi], &bf[njp][0]);
                    mma16816(acc[mi][2 * njp + 1], af[mi], &bf[njp][2]);
                }
        }
        CP_WAIT1();
        __syncthreads();
        if (++st == NSTG) st = 0;
    }

    // epilogue
    #pragma unroll
    for (int mi = 0; mi < 4; mi++) {
        #pragma unroll
        for (int nj = 0; nj < 8; nj++) {
            int row = m0 + wm * 64 + mi * 16 + g;
            int col = n0 + wn * 64 + nj * 8 + tig * 2;
            float2 v0, v1;
            v0.x = acc[mi][nj][0] * alpha; v0.y = acc[mi][nj][1] * alpha;
            v1.x = acc[mi][nj][2] * alpha; v1.y = acc[mi][nj][3] * alpha;
            if (CHALF) {
                __half* C = (__half*)Cv + (size_t)bz * strideC;
                *(__half2*)(C + (size_t)row * ldc + col) = __floats2half2_rn(v0.x, v0.y);
                *(__half2*)(C + (size_t)(row + 8) * ldc + col) = __floats2half2_rn(v1.x, v1.y);
            } else {
                float* C = (float*)Cv + (size_t)bz * strideC;
                *(float2*)(C + (size_t)row * ldc + col) = v0;
                *(float2*)(C + (size_t)(row + 8) * ldc + col) = v1;
            }
        }
    }
}

// ------------------------ causal softmax (sim fp32 -> P half) ---------------
// PV reads k < m0+256 => zero-fill P to 256 boundary.
__global__ __launch_bounds__(256) void softmax_causal(void) {
    int i = blockIdx.x;       // query row
    int h = blockIdx.y;       // head
    const float* row = g_sim + ((size_t)h * NSEQ + i) * NSEQ;
    __half* prow = g_p + ((size_t)h * NSEQ + i) * NSEQ;
    const float4* row4 = (const float4*)row;
    int L = i + 1;
    int Lr = (L + 255) & ~255;
    int nv = L >> 2;
    int tid = threadIdx.x;

    __shared__ float red[256];

    float m = -INFINITY;
    for (int j = tid; j < nv; j += 256) {
        float4 v = row4[j];
        m = fmaxf(m, fmaxf(fmaxf(v.x, v.y), fmaxf(v.z, v.w)));
    }
    for (int j = (nv << 2) + tid; j < L; j += 256) m = fmaxf(m, row[j]);
    red[tid] = m;
    __syncthreads();
    for (int off = 128; off > 0; off >>= 1) {
        if (tid < off) red[tid] = fmaxf(red[tid], red[tid + off]);
        __syncthreads();
    }
    m = red[0];
    __syncthreads();

    float s = 0.f;
    for (int j = tid; j < nv; j += 256) {
        float4 v = row4[j];
        v.x = expf(v.x - m); v.y = expf(v.y - m);
        v.z = expf(v.z - m); v.w = expf(v.w - m);
        // stash unscaled e into P (half); rescale pass follows
        *(__half2*)(prow + j * 4 + 0) = __floats2half2_rn(v.x, v.y);
        *(__half2*)(prow + j * 4 + 2) = __floats2half2_rn(v.z, v.w);
        s += v.x + v.y + v.z + v.w;
    }
    for (int j = (nv << 2) + tid; j < L; j += 256) {
        float e = expf(row[j] - m);
        prow[j] = __float2half_rn(e);
        s += e;
    }
    red[tid] = s;
    __syncthreads();
    for (int off = 128; off > 0; off >>= 1) {
        if (tid < off) red[tid] += red[tid + off];
        __syncthreads();
    }
    float inv = 1.0f / red[0];
    __half2 inv2 = __floats2half2_rn(inv, inv);

    for (int j = tid; j < nv * 2; j += 256) {   // half2 granularity over [0, 4*nv)
        __half2* p2 = (__half2*)prow + j;
        *p2 = __hmul2(*p2, inv2);
    }
    for (int j = (nv << 2) + tid; j < L; j += 256)
        prow[j] = __float2half_rn(__half2float(prow[j]) * inv);
    for (int j = L + tid; j < Lr; j += 256) prow[j] = __float2half_rn(0.f);
}

// --------------------------- SwiGLU activation ------------------------------
// proj half -> cat half cols [2048, 10240)
__global__ __launch_bounds__(256) void ff_act_kernel(void) {
    int row = blockIdx.y;
    int j2 = blockIdx.x * 256 + threadIdx.x;     // half2 index 0..4095
    const __half2* prow = (const __half2*)(g_projh + (size_t)row * FUSED_OUT);
    float2 xf = __half22float2(prow[FF_BASE / 2 + j2]);
    float2 gf = __half22float2(prow[GATE_BASE / 2 + j2]);
    float o0 = xf.x * (gf.x / (1.0f + expf(-gf.x)));
    float o1 = xf.y * (gf.y / (1.0f + expf(-gf.y)));
    ((__half2*)(g_cath + (size_t)row * CAT_K + ATTN_INNER))[j2] = __floats2half2_rn(o0, o1);
}

// ------------------------------- launch -------------------------------------
extern "C" void kernel_launch(void* const* d_in, const int* in_sizes, int n_in,
                              void* d_out, int out_size) {
    const float* x          = (const float*)d_in[0];
    const float* gamma      = (const float*)d_in[1];
    const float* w_fused    = (const float*)d_in[2];
    const float* w_attn_out = (const float*)d_in[3];
    const float* w_ff_out   = (const float*)d_in[4];
    float* out = (float*)d_out;

    __half *p_xnh, *p_projh, *p_p, *p_cath, *p_vt, *p_wft, *p_wcatt;
    float *p_sim;
    cudaGetSymbolAddress((void**)&p_xnh, g_xnh);
    cudaGetSymbolAddress((void**)&p_projh, g_projh);
    cudaGetSymbolAddress((void**)&p_sim, g_sim);
    cudaGetSymbolAddress((void**)&p_p, g_p);
    cudaGetSymbolAddress((void**)&p_cath, g_cath);
    cudaGetSymbolAddress((void**)&p_vt, g_vt);
    cudaGetSymbolAddress((void**)&p_wft, g_wft);
    cudaGetSymbolAddress((void**)&p_wcatt, g_wcatt);

    const int SMEM_DYN = NSTG * STAGE;   // 165888 B
    cudaFuncSetAttribute((const void*)mma_gemm<true,  false, false>,
                         cudaFuncAttributeMaxDynamicSharedMemorySize, SMEM_DYN);
    cudaFuncSetAttribute((const void*)mma_gemm<false, true,  false>,
                         cudaFuncAttributeMaxDynamicSharedMemorySize, SMEM_DYN);
    cudaFuncSetAttribute((const void*)mma_gemm<true,  false, true>,
                         cudaFuncAttributeMaxDynamicSharedMemorySize, SMEM_DYN);
    cudaFuncSetAttribute((const void*)mma_gemm<false, false, false>,
                         cudaFuncAttributeMaxDynamicSharedMemorySize, SMEM_DYN);

    const float scale = 0.08838834764831845f;  // 128^-0.5

    // 0. weight convert+transpose to [N][K] half
    wtrans_kernel<<<dim3(FUSED_OUT / 32, DIM / 32), 256>>>(
        w_fused, FUSED_OUT, p_wft, DIM, 0);
    wtrans_kernel<<<dim3(DIM / 32, ATTN_INNER / 32), 256>>>(
        w_attn_out, DIM, p_wcatt, CAT_K, 0);
    wtrans_kernel<<<dim3(DIM / 32, FF_INNER / 32), 256>>>(
        w_ff_out, DIM, p_wcatt, CAT_K, ATTN_INNER);

    // 1. LayerNorm -> xn half
    ln_kernel<<<NSEQ, 256>>>(x, gamma);

    // 2. proj = xn @ wf^T  -> proj half
    mma_gemm<true, false, false>
        <<<dim3(NSEQ / 256, FUSED_OUT / 128, 1), 256, SMEM_DYN>>>(
        p_xnh, DIM, 0, p_wft, DIM, 0, p_projh, FUSED_OUT, 0, DIM, 1.0f);

    // 2b. V transpose -> vt [DH][NSEQ] half
    vtrans_kernel<<<dim3(NSEQ / 32, DH / 32), 256>>>();

    // 3. sim = scale * Q_h @ Kmat^T  (fp32 out, causal tile skip)
    mma_gemm<false, true, false>
        <<<dim3(NSEQ / 256, NSEQ / 128, HEADS), 256, SMEM_DYN>>>(
        p_projh, FUSED_OUT, DH,
        p_projh + ATTN_INNER, FUSED_OUT, 0,
        p_sim, NSEQ, (long long)NSEQ * NSEQ, DH, scale);

    // 4. causal softmax: sim fp32 -> P half (zero-fill to 256 boundary)
    softmax_causal<<<dim3(NSEQ, HEADS), 256>>>();

    // 5. attn = P_h @ Vt^T -> cat cols [0,2048) half  (K clipped to diagonal)
    mma_gemm<true, false, true>
        <<<dim3(NSEQ / 256, 1, HEADS), 256, SMEM_DYN>>>(
        p_p, NSEQ, (long long)NSEQ * NSEQ,
        p_vt, NSEQ, 0,
        p_cath, CAT_K, DH, NSEQ, 1.0f);

    // 6. SwiGLU -> cat cols [2048, 10240) half
    ff_act_kernel<<<dim3(FF_INNER / 512, NSEQ), 256>>>();

    // 7. out = cat @ wcat^T  (fp32 out)
    mma_gemm<false, false, false>
        <<<dim3(NSEQ / 256, DIM / 128, 1), 256, SMEM_DYN>>>(
        p_cath, CAT_K, 0, p_wcatt, CAT_K, 0, out, DIM, 0, CAT_K, 1.0f);
}

// round 11
// speedup vs baseline: 2.7253x; 1.0718x over previous
#include <cuda_runtime.h>
#include <cuda_fp16.h>
#include <cstdint>
#include <math.h>

// ---------------------------------------------------------------------------
// ParallelTransformerBlock, fp16 tensor-core path (mma.sync m16n8k16 + ldmatrix
// + cp.async). fp32 accumulate everywhere.
// R10: sim stored half (in-place softmax buffer), single-pass register softmax,
//      4-stage cp.async pipeline.
// ---------------------------------------------------------------------------

#define NSEQ 2048
#define DIM 2048
#define DH 128
#define HEADS 16
#define ATTN_INNER 2048
#define FF_INNER 8192
#define FUSED_OUT 18688
#define FF_BASE 2304      // ATTN_INNER + 2*DH
#define GATE_BASE 10496   // FF_BASE + FF_INNER
#define CAT_K (ATTN_INNER + FF_INNER)   // 10240
#define LN_EPS 1e-5f

// ------------------------- device scratch (static) -------------------------
__device__ __half g_xnh[(size_t)NSEQ * DIM];                    // 8 MB
__device__ __half g_projh[(size_t)NSEQ * FUSED_OUT];            // 76.5 MB
__device__ __half g_p[(size_t)HEADS * NSEQ * NSEQ];             // 128 MB (sim -> P in place)
__device__ __half g_cath[(size_t)NSEQ * CAT_K];                 // 40 MB
__device__ __half g_vt[(size_t)DH * NSEQ];                      // 0.5 MB
__device__ __half g_wft[(size_t)FUSED_OUT * DIM];               // 76.5 MB  [N][K]
__device__ __half g_wcatt[(size_t)DIM * CAT_K];                 // 40 MB    [2048][10240]

// --------------------------- PTX helpers -----------------------------------
__device__ __forceinline__ uint32_t smem_u32(const void* p) {
    uint32_t a;
    asm("{ .reg .u64 t; cvta.to.shared.u64 t, %1; cvt.u32.u64 %0, t; }"
        : "=r"(a) : "l"(p));
    return a;
}

#define CP_ASYNC16(smaddr, gptr) \
    asm volatile("cp.async.cg.shared.global [%0], [%1], 16;" :: "r"(smaddr), "l"(gptr))
#define CP_COMMIT() asm volatile("cp.async.commit_group;" ::: "memory")
#define CP_WAIT2()  asm volatile("cp.async.wait_group 2;" ::: "memory")

#define LDSM4(r, addr) \
    asm volatile("ldmatrix.sync.aligned.m8n8.x4.shared.b16 {%0,%1,%2,%3}, [%4];" \
                 : "=r"((r)[0]), "=r"((r)[1]), "=r"((r)[2]), "=r"((r)[3]) \
                 : "r"(addr))

__device__ __forceinline__ void mma16816(float* d, const uint32_t* a, const uint32_t* b) {
    asm volatile(
        "mma.sync.aligned.m16n8k16.row.col.f32.f16.f16.f32 "
        "{%0,%1,%2,%3}, {%4,%5,%6,%7}, {%8,%9}, {%0,%1,%2,%3};"
        : "+f"(d[0]), "+f"(d[1]), "+f"(d[2]), "+f"(d[3])
        : "r"(a[0]), "r"(a[1]), "r"(a[2]), "r"(a[3]), "r"(b[0]), "r"(b[1]));
}

// ------------------------------ LayerNorm ----------------------------------
__global__ __launch_bounds__(256) void ln_kernel(const float* __restrict__ x,
                                                 const float* __restrict__ gamma) {
    int row = blockIdx.x;
    int tid = threadIdx.x;
    const float4* xr = (const float4*)(x + (size_t)row * DIM);
    __half2* out = (__half2*)(g_xnh + (size_t)row * DIM);
    const float4* g4 = (const float4*)gamma;

    float s = 0.f, sq = 0.f;
    float4 v[2];
    #pragma unroll
    for (int i = 0; i < 2; i++) {
        v[i] = xr[tid + 256 * i];
        s += v[i].x + v[i].y + v[i].z + v[i].w;
        sq += v[i].x * v[i].x + v[i].y * v[i].y + v[i].z * v[i].z + v[i].w * v[i].w;
    }
    __shared__ float red[256], red2[256];
    red[tid] = s; red2[tid] = sq;
    __syncthreads();
    for (int off = 128; off > 0; off >>= 1) {
        if (tid < off) { red[tid] += red[tid + off]; red2[tid] += red2[tid + off]; }
        __syncthreads();
    }
    float mu = red[0] * (1.0f / DIM);
    float var = red2[0] * (1.0f / DIM) - mu * mu;
    float inv = rsqrtf(var + LN_EPS);
    #pragma unroll
    for (int i = 0; i < 2; i++) {
        float4 g = g4[tid + 256 * i];
        float a0 = (v[i].x - mu) * inv * g.x;
        float a1 = (v[i].y - mu) * inv * g.y;
        float a2 = (v[i].z - mu) * inv * g.z;
        float a3 = (v[i].w - mu) * inv * g.w;
        out[(tid + 256 * i) * 2 + 0] = __floats2half2_rn(a0, a1);
        out[(tid + 256 * i) * 2 + 1] = __floats2half2_rn(a2, a3);
    }
}

// --------------- weight transpose + fp16 convert: [K,N] -> [N,K] ------------
__global__ __launch_bounds__(256) void wtrans_kernel(const float* __restrict__ src,
                                                     int N, __half* __restrict__ dst,
                                                     long long ldd, long long koff) {
    __shared__ float tile[32][33];
    int n0 = blockIdx.x * 32;
    int k0 = blockIdx.y * 32;
    int tx = threadIdx.x & 31, ty = threadIdx.x >> 5;   // 32 x 8
    #pragma unroll
    for (int i = 0; i < 4; i++)
        tile[ty + 8 * i][tx] = src[(size_t)(k0 + ty + 8 * i) * N + n0 + tx];
    __syncthreads();
    #pragma unroll
    for (int i = 0; i < 4; i++)
        dst[(size_t)(n0 + ty + 8 * i) * ldd + koff + k0 + tx] =
            __float2half_rn(tile[tx][ty + 8 * i]);
}

// ---------------- V transpose (half->half): proj cols -> [DH][NSEQ] ---------
__global__ __launch_bounds__(256) void vtrans_kernel(void) {
    __shared__ __half tile[32][33];
    int s0 = blockIdx.x * 32;
    int d0 = blockIdx.y * 32;
    int tx = threadIdx.x & 31, ty = threadIdx.x >> 5;
    #pragma unroll
    for (int i = 0; i < 4; i++)
        tile[ty + 8 * i][tx] =
            g_projh[(size_t)(s0 + ty + 8 * i) * FUSED_OUT + ATTN_INNER + DH + d0 + tx];
    __syncthreads();
    #pragma unroll
    for (int i = 0; i < 4; i++)
        g_vt[(size_t)(d0 + ty + 8 * i) * NSEQ + s0 + tx] = tile[tx][ty + 8 * i];
}

// ------------------------- fp16 tensor-core GEMM ----------------------------
// C[M,N] = alpha * A[M,K] @ B^T, A half [M][K] k-contig, B half [N][K] k-contig.
// blockIdx.x = M tile (256), blockIdx.y = N tile (128), z = batch.
// 256x128x64 CTA tile, 4-stage cp.async, 256 threads: 8 warps 4(m) x 2(n),
// each warp 64x64 (4x8 m16n8k16), fragments via ldmatrix.x4.
#define ROWB   144                      // bytes per smem row (64 halves + 8 pad)
#define ABYTES (256 * ROWB)             // 36864
#define BBYTES (128 * ROWB)             // 18432
#define STAGE  (ABYTES + BBYTES)        // 55296
#define NSTG   4

template <bool CHALF, bool CAUSAL_QK, bool CAUSAL_PV>
__global__ __launch_bounds__(256, 1)
void mma_gemm(const __half* __restrict__ A, long long lda, long long strideA,
              const __half* __restrict__ B, long long ldb, long long strideB,
              void* __restrict__ Cv, long long ldc, long long strideC,
              int K, float alpha)
{
    const int bx = blockIdx.x;   // m tile
    const int by = blockIdx.y;   // n tile
    const int bz = blockIdx.z;
    if (CAUSAL_QK && by > 2 * bx + 1) return;   // tile fully above diagonal

    A += (size_t)bz * strideA;
    B += (size_t)bz * strideB;

    const int m0 = bx * 256;
    const int n0 = by * 128;
    const int K_eff = CAUSAL_PV ? min(K, m0 + 256) : K;
    const int NT = K_eff >> 6;                  // 64-wide K chunks

    extern __shared__ char smem[];
    const uint32_t sm_u = smem_u32(smem);

    const int tid = threadIdx.x;
    const int lane = tid & 31;
    const int warp = tid >> 5;
    const int wm = warp & 3;          // 0..3  (64 rows each)
    const int wn = warp >> 2;         // 0..1  (64 cols each)
    const int g = lane >> 2;          // 0..7
    const int tig = lane & 3;         // 0..3

    // ldmatrix per-lane byte offsets within a stage
    const uint32_t a_off = (uint32_t)((wm * 64 + (lane & 15)) * ROWB + ((lane >> 4) << 4));
    const uint32_t b_off = (uint32_t)(ABYTES +
        (wn * 64 + (lane & 7) + ((lane >> 4) << 3)) * ROWB + (((lane >> 3) & 1) << 4));

    float acc[4][8][4];
    #pragma unroll
    for (int i = 0; i < 4; i++)
        #pragma unroll
        for (int j = 0; j < 8; j++)
            #pragma unroll
            for (int r = 0; r < 4; r++) acc[i][j][r] = 0.f;

    auto load_stage = [&](int st, int t) {
        const uint32_t abase = sm_u + st * STAGE;
        const uint32_t bbase = abase + ABYTES;
        const long long kk = (long long)t << 6;
        #pragma unroll
        for (int i = 0; i < 8; i++) {              // A: 256 rows x 128B
            int idx = tid + 256 * i;
            int row = idx >> 3, seg = idx & 7;
            uint32_t so = abase + (uint32_t)(row * ROWB + seg * 16);
            const __half* gp = A + (size_t)(m0 + row) * lda + kk + seg * 8;
            CP_ASYNC16(so, gp);
        }
        #pragma unroll
        for (int i = 0; i < 4; i++) {              // B: 128 rows x 128B
            int idx = tid + 256 * i;
            int row = idx >> 3, seg = idx & 7;
            uint32_t so = bbase + (uint32_t)(row * ROWB + seg * 16);
            const __half* gp = B + (size_t)(n0 + row) * ldb + kk + seg * 8;
            CP_ASYNC16(so, gp);
        }
    };

    #pragma unroll
    for (int s = 0; s < NSTG - 1; s++) {
        if (s < NT) load_stage(s, s);
        CP_COMMIT();
    }
    CP_WAIT2();
    __syncthreads();

    int st = 0;
    for (int t = 0; t < NT; t++) {
        int lt = t + NSTG - 1;
        int lst = st + NSTG - 1; if (lst >= NSTG) lst -= NSTG;
        if (lt < NT) load_stage(lst, lt);
        CP_COMMIT();

        const uint32_t abase = sm_u + st * STAGE;

        #pragma unroll
        for (int ks = 0; ks < 4; ks++) {           // 4 x k16 steps
            uint32_t af[4][4], bf[4][4];
            #pragma unroll
            for (int mi = 0; mi < 4; mi++)
                LDSM4(af[mi], abase + a_off + mi * (16 * ROWB) + ks * 32);
            #pragma unroll
            for (int njp = 0; njp < 4; njp++)
                LDSM4(bf[njp], abase + b_off + njp * (16 * ROWB) + ks * 32);
            #pragma unroll
            for (int mi = 0; mi < 4; mi++)
                #pragma unroll
                for (int njp = 0; njp < 4; njp++) {
                    mma16816(acc[mi][2 * njp + 0], af[mi], &bf[njp][0]);
                    mma16816(acc[mi][2 * njp + 1], af[mi], &bf[njp][2]);
                }
        }
        CP_WAIT2();
        __syncthreads();
        if (++st == NSTG) st = 0;
    }

    // epilogue
    #pragma unroll
    for (int mi = 0; mi < 4; mi++) {
        #pragma unroll
        for (int nj = 0; nj < 8; nj++) {
            int row = m0 + wm * 64 + mi * 16 + g;
            int col = n0 + wn * 64 + nj * 8 + tig * 2;
            float2 v0, v1;
            v0.x = acc[mi][nj][0] * alpha; v0.y = acc[mi][nj][1] * alpha;
            v1.x = acc[mi][nj][2] * alpha; v1.y = acc[mi][nj][3] * alpha;
            if (CHALF) {
                __half* C = (__half*)Cv + (size_t)bz * strideC;
                *(__half2*)(C + (size_t)row * ldc + col) = __floats2half2_rn(v0.x, v0.y);
                *(__half2*)(C + (size_t)(row + 8) * ldc + col) = __floats2half2_rn(v1.x, v1.y);
            } else {
                float* C = (float*)Cv + (size_t)bz * strideC;
                *(float2*)(C + (size_t)row * ldc + col) = v0;
                *(float2*)(C + (size_t)(row + 8) * ldc + col) = v1;
            }
        }
    }
}

// ---------------- causal softmax (half, in place, single pass) ---------------
// Row of 2048 halves; 256 threads x 8 elems. Reads only [0, Lr), writes [0, Lr)
// where Lr = roundup256(L) (PV clips K to that). Elements >= L become 0.
__global__ __launch_bounds__(256) void softmax_causal(void) {
    int i = blockIdx.x;       // query row
    int h = blockIdx.y;       // head
    __half* row = g_p + ((size_t)h * NSEQ + i) * NSEQ;
    const int L = i + 1;
    const int Lr = (L + 255) & ~255;
    const int tid = threadIdx.x;
    const int j0 = tid * 8;
    const int lane = tid & 31;
    const int wrp = tid >> 5;

    __shared__ float red[8];

    float v[8];
    if (j0 < Lr) {
        int4 raw = *(const int4*)(row + j0);
        const __half2* h2 = (const __half2*)&raw;
        #pragma unroll
        for (int k = 0; k < 4; k++) {
            float2 f = __half22float2(h2[k]);
            v[2 * k] = f.x; v[2 * k + 1] = f.y;
        }
    } else {
        #pragma unroll
        for (int k = 0; k < 8; k++) v[k] = -INFINITY;
    }
    #pragma unroll
    for (int k = 0; k < 8; k++) v[k] = (j0 + k < L) ? v[k] : -INFINITY;

    // max reduce
    float m = v[0];
    #pragma unroll
    for (int k = 1; k < 8; k++) m = fmaxf(m, v[k]);
    #pragma unroll
    for (int off = 16; off > 0; off >>= 1)
        m = fmaxf(m, __shfl_xor_sync(0xffffffffu, m, off));
    if (lane == 0) red[wrp] = m;
    __syncthreads();
    m = red[0];
    #pragma unroll
    for (int w = 1; w < 8; w++) m = fmaxf(m, red[w]);
    __syncthreads();

    // exp + sum
    float e[8];
    float s = 0.f;
    #pragma unroll
    for (int k = 0; k < 8; k++) {
        e[k] = (j0 + k < L) ? expf(v[k] - m) : 0.f;
        s += e[k];
    }
    #pragma unroll
    for (int off = 16; off > 0; off >>= 1)
        s += __shfl_xor_sync(0xffffffffu, s, off);
    if (lane == 0) red[wrp] = s;
    __syncthreads();
    s = red[0];
    #pragma unroll
    for (int w = 1; w < 8; w++) s += red[w];
    float inv = 1.0f / s;

    if (j0 < Lr) {
        int4 raw;
        __half2* h2 = (__half2*)&raw;
        #pragma unroll
        for (int k = 0; k < 4; k++)
            h2[k] = __floats2half2_rn(e[2 * k] * inv, e[2 * k + 1] * inv);
        *(int4*)(row + j0) = raw;
    }
}

// --------------------------- SwiGLU activation ------------------------------
// proj half -> cat half cols [2048, 10240)
__global__ __launch_bounds__(256) void ff_act_kernel(void) {
    int row = blockIdx.y;
    int j2 = blockIdx.x * 256 + threadIdx.x;     // half2 index 0..4095
    const __half2* prow = (const __half2*)(g_projh + (size_t)row * FUSED_OUT);
    float2 xf = __half22float2(prow[FF_BASE / 2 + j2]);
    float2 gf = __half22float2(prow[GATE_BASE / 2 + j2]);
    float o0 = xf.x * (gf.x / (1.0f + expf(-gf.x)));
    float o1 = xf.y * (gf.y / (1.0f + expf(-gf.y)));
    ((__half2*)(g_cath + (size_t)row * CAT_K + ATTN_INNER))[j2] = __floats2half2_rn(o0, o1);
}

// ------------------------------- launch -------------------------------------
extern "C" void kernel_launch(void* const* d_in, const int* in_sizes, int n_in,
                              void* d_out, int out_size) {
    const float* x          = (const float*)d_in[0];
    const float* gamma      = (const float*)d_in[1];
    const float* w_fused    = (const float*)d_in[2];
    const float* w_attn_out = (const float*)d_in[3];
    const float* w_ff_out   = (const float*)d_in[4];
    float* out = (float*)d_out;

    __half *p_xnh, *p_projh, *p_p, *p_cath, *p_vt, *p_wft, *p_wcatt;
    cudaGetSymbolAddress((void**)&p_xnh, g_xnh);
    cudaGetSymbolAddress((void**)&p_projh, g_projh);
    cudaGetSymbolAddress((void**)&p_p, g_p);
    cudaGetSymbolAddress((void**)&p_cath, g_cath);
    cudaGetSymbolAddress((void**)&p_vt, g_vt);
    cudaGetSymbolAddress((void**)&p_wft, g_wft);
    cudaGetSymbolAddress((void**)&p_wcatt, g_wcatt);

    const int SMEM_DYN = NSTG * STAGE;   // 221184 B
    cudaFuncSetAttribute((const void*)mma_gemm<true,  false, false>,
                         cudaFuncAttributeMaxDynamicSharedMemorySize, SMEM_DYN);
    cudaFuncSetAttribute((const void*)mma_gemm<true,  true,  false>,
                         cudaFuncAttributeMaxDynamicSharedMemorySize, SMEM_DYN);
    cudaFuncSetAttribute((const void*)mma_gemm<true,  false, true>,
                         cudaFuncAttributeMaxDynamicSharedMemorySize, SMEM_DYN);
    cudaFuncSetAttribute((const void*)mma_gemm<false, false, false>,
                         cudaFuncAttributeMaxDynamicSharedMemorySize, SMEM_DYN);

    const float scale = 0.08838834764831845f;  // 128^-0.5

    // 0. weight convert+transpose to [N][K] half
    wtrans_kernel<<<dim3(FUSED_OUT / 32, DIM / 32), 256>>>(
        w_fused, FUSED_OUT, p_wft, DIM, 0);
    wtrans_kernel<<<dim3(DIM / 32, ATTN_INNER / 32), 256>>>(
        w_attn_out, DIM, p_wcatt, CAT_K, 0);
    wtrans_kernel<<<dim3(DIM / 32, FF_INNER / 32), 256>>>(
        w_ff_out, DIM, p_wcatt, CAT_K, ATTN_INNER);

    // 1. LayerNorm -> xn half
    ln_kernel<<<NSEQ, 256>>>(x, gamma);

    // 2. proj = xn @ wf^T  -> proj half
    mma_gemm<true, false, false>
        <<<dim3(NSEQ / 256, FUSED_OUT / 128, 1), 256, SMEM_DYN>>>(
        p_xnh, DIM, 0, p_wft, DIM, 0, p_projh, FUSED_OUT, 0, DIM, 1.0f);

    // 2b. V transpose -> vt [DH][NSEQ] half
    vtrans_kernel<<<dim3(NSEQ / 32, DH / 32), 256>>>();

    // 3. sim = scale * Q_h @ Kmat^T  -> half, straight into P buffer
    mma_gemm<true, true, false>
        <<<dim3(NSEQ / 256, NSEQ / 128, HEADS), 256, SMEM_DYN>>>(
        p_projh, FUSED_OUT, DH,
        p_projh + ATTN_INNER, FUSED_OUT, 0,
        p_p, NSEQ, (long long)NSEQ * NSEQ, DH, scale);

    // 4. causal softmax in place (single pass, register resident)
    softmax_causal<<<dim3(NSEQ, HEADS), 256>>>();

    // 5. attn = P_h @ Vt^T -> cat cols [0,2048) half  (K clipped to diagonal)
    mma_gemm<true, false, true>
        <<<dim3(NSEQ / 256, 1, HEADS), 256, SMEM_DYN>>>(
        p_p, NSEQ, (long long)NSEQ * NSEQ,
        p_vt, NSEQ, 0,
        p_cath, CAT_K, DH, NSEQ, 1.0f);

    // 6. SwiGLU -> cat cols [2048, 10240) half
    ff_act_kernel<<<dim3(FF_INNER / 512, NSEQ), 256>>>();

    // 7. out = cat @ wcat^T  (fp32 out)
    mma_gemm<false, false, false>
        <<<dim3(NSEQ / 256, DIM / 128, 1), 256, SMEM_DYN>>>(
        p_cath, CAT_K, 0, p_wcatt, CAT_K, 0, out, DIM, 0, CAT_K, 1.0f);
}

// round 13
// speedup vs baseline: 2.9541x; 1.0840x over previous
#include <cuda_runtime.h>
#include <cuda_fp16.h>
#include <cstdint>
#include <math.h>

// ---------------------------------------------------------------------------
// ParallelTransformerBlock, fp16 tensor-core path (mma.sync m16n8k16 + ldmatrix
// + cp.async). fp32 accumulate everywhere.
// R13: R12 flash-attention fused kernel, fixed __half2 bit-cast helper.
// ---------------------------------------------------------------------------

#define NSEQ 2048
#define DIM 2048
#define DH 128
#define HEADS 16
#define ATTN_INNER 2048
#define FF_INNER 8192
#define FUSED_OUT 18688
#define FF_BASE 2304      // ATTN_INNER + 2*DH
#define GATE_BASE 10496   // FF_BASE + FF_INNER
#define CAT_K (ATTN_INNER + FF_INNER)   // 10240
#define LN_EPS 1e-5f

// ------------------------- device scratch (static) -------------------------
__device__ __half g_xnh[(size_t)NSEQ * DIM];                    // 8 MB
__device__ __half g_projh[(size_t)NSEQ * FUSED_OUT];            // 76.5 MB
__device__ __half g_cath[(size_t)NSEQ * CAT_K];                 // 40 MB
__device__ __half g_vt[(size_t)DH * NSEQ];                      // 0.5 MB
__device__ __half g_wft[(size_t)FUSED_OUT * DIM];               // 76.5 MB  [N][K]
__device__ __half g_wcatt[(size_t)DIM * CAT_K];                 // 40 MB    [2048][10240]

// --------------------------- PTX helpers -----------------------------------
__device__ __forceinline__ uint32_t smem_u32(const void* p) {
    uint32_t a;
    asm("{ .reg .u64 t; cvta.to.shared.u64 t, %1; cvt.u32.u64 %0, t; }"
        : "=r"(a) : "l"(p));
    return a;
}

__device__ __forceinline__ uint32_t h2_u32(__half2 h) {
    union { __half2 h; uint32_t u; } cvt;
    cvt.h = h;
    return cvt.u;
}

#define CP_ASYNC16(smaddr, gptr) \
    asm volatile("cp.async.cg.shared.global [%0], [%1], 16;" :: "r"(smaddr), "l"(gptr))
#define CP_COMMIT() asm volatile("cp.async.commit_group;" ::: "memory")
#define CP_WAIT0()  asm volatile("cp.async.wait_group 0;" ::: "memory")
#define CP_WAIT1()  asm volatile("cp.async.wait_group 1;" ::: "memory")
#define CP_WAIT2()  asm volatile("cp.async.wait_group 2;" ::: "memory")

#define LDSM4(r, addr) \
    asm volatile("ldmatrix.sync.aligned.m8n8.x4.shared.b16 {%0,%1,%2,%3}, [%4];" \
                 : "=r"((r)[0]), "=r"((r)[1]), "=r"((r)[2]), "=r"((r)[3]) \
                 : "r"(addr))

__device__ __forceinline__ void mma16816(float* d, const uint32_t* a, const uint32_t* b) {
    asm volatile(
        "mma.sync.aligned.m16n8k16.row.col.f32.f16.f16.f32 "
        "{%0,%1,%2,%3}, {%4,%5,%6,%7}, {%8,%9}, {%0,%1,%2,%3};"
        : "+f"(d[0]), "+f"(d[1]), "+f"(d[2]), "+f"(d[3])
        : "r"(a[0]), "r"(a[1]), "r"(a[2]), "r"(a[3]), "r"(b[0]), "r"(b[1]));
}

// ------------------------------ LayerNorm ----------------------------------
__global__ __launch_bounds__(256) void ln_kernel(const float* __restrict__ x,
                                                 const float* __restrict__ gamma) {
    int row = blockIdx.x;
    int tid = threadIdx.x;
    const float4* xr = (const float4*)(x + (size_t)row * DIM);
    __half2* out = (__half2*)(g_xnh + (size_t)row * DIM);
    const float4* g4 = (const float4*)gamma;

    float s = 0.f, sq = 0.f;
    float4 v[2];
    #pragma unroll
    for (int i = 0; i < 2; i++) {
        v[i] = xr[tid + 256 * i];
        s += v[i].x + v[i].y + v[i].z + v[i].w;
        sq += v[i].x * v[i].x + v[i].y * v[i].y + v[i].z * v[i].z + v[i].w * v[i].w;
    }
    __shared__ float red[256], red2[256];
    red[tid] = s; red2[tid] = sq;
    __syncthreads();
    for (int off = 128; off > 0; off >>= 1) {
        if (tid < off) { red[tid] += red[tid + off]; red2[tid] += red2[tid + off]; }
        __syncthreads();
    }
    float mu = red[0] * (1.0f / DIM);
    float var = red2[0] * (1.0f / DIM) - mu * mu;
    float inv = rsqrtf(var + LN_EPS);
    #pragma unroll
    for (int i = 0; i < 2; i++) {
        float4 g = g4[tid + 256 * i];
        float a0 = (v[i].x - mu) * inv * g.x;
        float a1 = (v[i].y - mu) * inv * g.y;
        float a2 = (v[i].z - mu) * inv * g.z;
        float a3 = (v[i].w - mu) * inv * g.w;
        out[(tid + 256 * i) * 2 + 0] = __floats2half2_rn(a0, a1);
        out[(tid + 256 * i) * 2 + 1] = __floats2half2_rn(a2, a3);
    }
}

// --------------- weight transpose + fp16 convert: [K,N] -> [N,K] ------------
__global__ __launch_bounds__(256) void wtrans_kernel(const float* __restrict__ src,
                                                     int N, __half* __restrict__ dst,
                                                     long long ldd, long long koff) {
    __shared__ float tile[32][33];
    int n0 = blockIdx.x * 32;
    int k0 = blockIdx.y * 32;
    int tx = threadIdx.x & 31, ty = threadIdx.x >> 5;   // 32 x 8
    #pragma unroll
    for (int i = 0; i < 4; i++)
        tile[ty + 8 * i][tx] = src[(size_t)(k0 + ty + 8 * i) * N + n0 + tx];
    __syncthreads();
    #pragma unroll
    for (int i = 0; i < 4; i++)
        dst[(size_t)(n0 + ty + 8 * i) * ldd + koff + k0 + tx] =
            __float2half_rn(tile[tx][ty + 8 * i]);
}

// ---------------- V transpose (half->half): proj cols -> [DH][NSEQ] ---------
__global__ __launch_bounds__(256) void vtrans_kernel(void) {
    __shared__ __half tile[32][33];
    int s0 = blockIdx.x * 32;
    int d0 = blockIdx.y * 32;
    int tx = threadIdx.x & 31, ty = threadIdx.x >> 5;
    #pragma unroll
    for (int i = 0; i < 4; i++)
        tile[ty + 8 * i][tx] =
            g_projh[(size_t)(s0 + ty + 8 * i) * FUSED_OUT + ATTN_INNER + DH + d0 + tx];
    __syncthreads();
    #pragma unroll
    for (int i = 0; i < 4; i++)
        g_vt[(size_t)(d0 + ty + 8 * i) * NSEQ + s0 + tx] = tile[tx][ty + 8 * i];
}

// ------------------------- fp16 tensor-core GEMM ----------------------------
// C[M,N] = A[M,K] @ B^T, A half [M][K] k-contig, B half [N][K] k-contig.
// 256x128x64 CTA tile, 4-stage cp.async, 256 threads: 8 warps 4(m) x 2(n).
#define ROWB   144                      // bytes per smem row (64 halves + 8 pad)
#define ABYTES (256 * ROWB)             // 36864
#define BBYTES (128 * ROWB)             // 18432
#define STAGE  (ABYTES + BBYTES)        // 55296
#define NSTG   4

template <bool CHALF>
__global__ __launch_bounds__(256, 1)
void mma_gemm(const __half* __restrict__ A, long long lda,
              const __half* __restrict__ B, long long ldb,
              void* __restrict__ Cv, long long ldc,
              int K)
{
    const int bx = blockIdx.x;   // m tile
    const int by = blockIdx.y;   // n tile

    const int m0 = bx * 256;
    const int n0 = by * 128;
    const int NT = K >> 6;

    extern __shared__ char smem[];
    const uint32_t sm_u = smem_u32(smem);

    const int tid = threadIdx.x;
    const int lane = tid & 31;
    const int warp = tid >> 5;
    const int wm = warp & 3;
    const int wn = warp >> 2;
    const int g = lane >> 2;
    const int tig = lane & 3;

    const uint32_t a_off = (uint32_t)((wm * 64 + (lane & 15)) * ROWB + ((lane >> 4) << 4));
    const uint32_t b_off = (uint32_t)(ABYTES +
        (wn * 64 + (lane & 7) + ((lane >> 4) << 3)) * ROWB + (((lane >> 3) & 1) << 4));

    float acc[4][8][4];
    #pragma unroll
    for (int i = 0; i < 4; i++)
        #pragma unroll
        for (int j = 0; j < 8; j++)
            #pragma unroll
            for (int r = 0; r < 4; r++) acc[i][j][r] = 0.f;

    auto load_stage = [&](int st, int t) {
        const uint32_t abase = sm_u + st * STAGE;
        const uint32_t bbase = abase + ABYTES;
        const long long kk = (long long)t << 6;
        #pragma unroll
        for (int i = 0; i < 8; i++) {
            int idx = tid + 256 * i;
            int row = idx >> 3, seg = idx & 7;
            uint32_t so = abase + (uint32_t)(row * ROWB + seg * 16);
            const __half* gp = A + (size_t)(m0 + row) * lda + kk + seg * 8;
            CP_ASYNC16(so, gp);
        }
        #pragma unroll
        for (int i = 0; i < 4; i++) {
            int idx = tid + 256 * i;
            int row = idx >> 3, seg = idx & 7;
            uint32_t so = bbase + (uint32_t)(row * ROWB + seg * 16);
            const __half* gp = B + (size_t)(n0 + row) * ldb + kk + seg * 8;
            CP_ASYNC16(so, gp);
        }
    };

    #pragma unroll
    for (int s = 0; s < NSTG - 1; s++) {
        if (s < NT) load_stage(s, s);
        CP_COMMIT();
    }
    CP_WAIT2();
    __syncthreads();

    int st = 0;
    for (int t = 0; t < NT; t++) {
        int lt = t + NSTG - 1;
        int lst = st + NSTG - 1; if (lst >= NSTG) lst -= NSTG;
        if (lt < NT) load_stage(lst, lt);
        CP_COMMIT();

        const uint32_t abase = sm_u + st * STAGE;

        #pragma unroll
        for (int ks = 0; ks < 4; ks++) {
            uint32_t af[4][4], bf[4][4];
            #pragma unroll
            for (int mi = 0; mi < 4; mi++)
                LDSM4(af[mi], abase + a_off + mi * (16 * ROWB) + ks * 32);
            #pragma unroll
            for (int njp = 0; njp < 4; njp++)
                LDSM4(bf[njp], abase + b_off + njp * (16 * ROWB) + ks * 32);
            #pragma unroll
            for (int mi = 0; mi < 4; mi++)
                #pragma unroll
                for (int njp = 0; njp < 4; njp++) {
                    mma16816(acc[mi][2 * njp + 0], af[mi], &bf[njp][0]);
                    mma16816(acc[mi][2 * njp + 1], af[mi], &bf[njp][2]);
                }
        }
        CP_WAIT2();
        __syncthreads();
        if (++st == NSTG) st = 0;
    }

    #pragma unroll
    for (int mi = 0; mi < 4; mi++) {
        #pragma unroll
        for (int nj = 0; nj < 8; nj++) {
            int row = m0 + wm * 64 + mi * 16 + g;
            int col = n0 + wn * 64 + nj * 8 + tig * 2;
            if (CHALF) {
                __half* C = (__half*)Cv;
                *(__half2*)(C + (size_t)row * ldc + col) =
                    __floats2half2_rn(acc[mi][nj][0], acc[mi][nj][1]);
                *(__half2*)(C + (size_t)(row + 8) * ldc + col) =
                    __floats2half2_rn(acc[mi][nj][2], acc[mi][nj][3]);
            } else {
                float* C = (float*)Cv;
                *(float2*)(C + (size_t)row * ldc + col) =
                    make_float2(acc[mi][nj][0], acc[mi][nj][1]);
                *(float2*)(C + (size_t)(row + 8) * ldc + col) =
                    make_float2(acc[mi][nj][2], acc[mi][nj][3]);
            }
        }
    }
}

// ------------------------- fused flash attention -----------------------------
// grid (32 qblocks, 16 heads), 128 threads (4 warps, 16 q-rows each).
// Per CTA: Q[64x128] pre-scaled in smem; loop j over 64-wide K/V blocks
// (double-buffered cp.async); S=Q K^T fp32 frags; online softmax (intra-warp);
// P->fp16 A-frags in registers; O += P V  (V from g_vt, [dh][seq]).
#define FQ_ROWB 272                     // Q/K smem row: 128 halves + 8 pad
#define FV_ROWB 144                     // Vt smem row: 64 halves + 8 pad
#define FQ_BYTES (64 * FQ_ROWB)         // 17408
#define FK_BYTES (64 * FQ_ROWB)         // 17408
#define FV_BYTES (128 * FV_ROWB)        // 18432
#define FSTAGE   (FK_BYTES + FV_BYTES)  // 35840
#define FSMEM    (FQ_BYTES + 2 * FSTAGE)// 89088

__global__ __launch_bounds__(128, 2)
void flash_attn(void) {
    const int qb = gridDim.x - 1 - blockIdx.x;      // big workloads first
    const int h = blockIdx.y;
    const int q0 = qb * 64;
    const int jmax = qb;                             // k-blocks 0..qb

    extern __shared__ char smem[];
    const uint32_t sm_u = smem_u32(smem);
    const uint32_t kbase0 = sm_u + FQ_BYTES;

    const int tid = threadIdx.x;
    const int lane = tid & 31;
    const int w = tid >> 5;

    const __half* Qg = g_projh + (size_t)h * DH;                 // row stride FUSED_OUT
    const __half* Kg = g_projh + ATTN_INNER;
    const __half* Vtg = g_vt;

    // ---- load + pre-scale Q into smem ----
    {
        const float scale = 0.08838834764831845f;
        for (int i = tid; i < 64 * 64; i += 128) {   // half2 granularity
            int row = i >> 6, c2 = i & 63;
            __half2 qv = *(const __half2*)(Qg + (size_t)(q0 + row) * FUSED_OUT + c2 * 2);
            float2 f = __half22float2(qv);
            *(__half2*)(smem + row * FQ_ROWB + c2 * 4) =
                __floats2half2_rn(f.x * scale, f.y * scale);
        }
    }

    // ---- stage loader (K block + Vt block for k-positions [j*64, j*64+64)) ----
    auto load_stage = [&](int buf, int j) {
        const uint32_t kb = kbase0 + buf * FSTAGE;
        const uint32_t vb = kb + FK_BYTES;
        const int kp0 = j * 64;
        #pragma unroll
        for (int i = 0; i < 8; i++) {                // K: 64 rows x 256B
            int idx = tid + 128 * i;
            int row = idx >> 4, seg = idx & 15;
            CP_ASYNC16(kb + (uint32_t)(row * FQ_ROWB + seg * 16),
                       Kg + (size_t)(kp0 + row) * FUSED_OUT + seg * 8);
        }
        #pragma unroll
        for (int i = 0; i < 8; i++) {                // Vt: 128 rows x 128B
            int idx = tid + 128 * i;
            int row = idx >> 3, seg = idx & 7;
            CP_ASYNC16(vb + (uint32_t)(row * FV_ROWB + seg * 16),
                       Vtg + (size_t)row * NSEQ + kp0 + seg * 8);
        }
    };

    load_stage(0, 0);
    CP_COMMIT();
    __syncthreads();    // Q smem ready (also covers ldmatrix below)

    // ---- Q fragments (pre-scaled) ----
    uint32_t qf[8][4];
    {
        const uint32_t qoff = (uint32_t)((w * 16 + (lane & 15)) * FQ_ROWB + ((lane >> 4) << 4));
        #pragma unroll
        for (int kf = 0; kf < 8; kf++)
            LDSM4(qf[kf], sm_u + qoff + kf * 32);
    }

    // ---- state ----
    float oacc[16][4];
    #pragma unroll
    for (int i = 0; i < 16; i++)
        #pragma unroll
        for (int r = 0; r < 4; r++) oacc[i][r] = 0.f;
    float mrow0 = -INFINITY, mrow1 = -INFINITY;
    float lrow0 = 0.f, lrow1 = 0.f;

    const uint32_t kfrag_off = (uint32_t)(((lane & 7) + ((lane >> 4) << 3)) * FQ_ROWB +
                                          (((lane >> 3) & 1) << 4));
    const uint32_t vfrag_off = (uint32_t)(((lane & 7) + ((lane >> 4) << 3)) * FV_ROWB +
                                          (((lane >> 3) & 1) << 4));

    for (int j = 0; j <= jmax; j++) {
        int buf = j & 1;
        if (j < jmax) { load_stage(buf ^ 1, j + 1); CP_COMMIT(); }
        if (j < jmax) { CP_WAIT1(); } else { CP_WAIT0(); }
        __syncthreads();

        const uint32_t kb = kbase0 + buf * FSTAGE;
        const uint32_t vb = kb + FK_BYTES;

        // ---- S = Q K^T (16 rows x 64 cols per warp) ----
        float sacc[8][4];
        #pragma unroll
        for (int nj = 0; nj < 8; nj++)
            #pragma unroll
            for (int r = 0; r < 4; r++) sacc[nj][r] = 0.f;
        #pragma unroll
        for (int njp = 0; njp < 4; njp++) {
            #pragma unroll
            for (int kf = 0; kf < 8; kf++) {
                uint32_t bf[4];
                LDSM4(bf, kb + kfrag_off + njp * (16 * FQ_ROWB) + kf * 32);
                mma16816(sacc[2 * njp + 0], qf[kf], &bf[0]);
                mma16816(sacc[2 * njp + 1], qf[kf], &bf[2]);
            }
        }

        // ---- causal mask on diagonal block ----
        if (j == jmax) {
            int r0 = q0 + w * 16 + (lane >> 2);
            int cb = j * 64 + (lane & 3) * 2;
            #pragma unroll
            for (int nj = 0; nj < 8; nj++) {
                int c = cb + nj * 8;
                if (c > r0)     sacc[nj][0] = -1e30f;
                if (c + 1 > r0) sacc[nj][1] = -1e30f;
                if (c > r0 + 8)     sacc[nj][2] = -1e30f;
                if (c + 1 > r0 + 8) sacc[nj][3] = -1e30f;
            }
        }

        // ---- online softmax (rows fully within warp; reduce over lane&3) ----
        float bm0 = sacc[0][0], bm1 = sacc[0][2];
        #pragma unroll
        for (int nj = 0; nj < 8; nj++) {
            bm0 = fmaxf(bm0, fmaxf(sacc[nj][0], sacc[nj][1]));
            bm1 = fmaxf(bm1, fmaxf(sacc[nj][2], sacc[nj][3]));
        }
        #pragma unroll
        for (int off = 1; off <= 2; off <<= 1) {
            bm0 = fmaxf(bm0, __shfl_xor_sync(0xffffffffu, bm0, off));
            bm1 = fmaxf(bm1, __shfl_xor_sync(0xffffffffu, bm1, off));
        }
        float mnew0 = fmaxf(mrow0, bm0);
        float mnew1 = fmaxf(mrow1, bm1);
        float alpha0 = __expf(mrow0 - mnew0);
        float alpha1 = __expf(mrow1 - mnew1);
        mrow0 = mnew0; mrow1 = mnew1;

        uint32_t paf[4][4];
        float s0 = 0.f, s1 = 0.f;
        #pragma unroll
        for (int njp = 0; njp < 4; njp++) {
            float p00 = __expf(sacc[2 * njp + 0][0] - mnew0);
            float p01 = __expf(sacc[2 * njp + 0][1] - mnew0);
            float p02 = __expf(sacc[2 * njp + 0][2] - mnew1);
            float p03 = __expf(sacc[2 * njp + 0][3] - mnew1);
            float p10 = __expf(sacc[2 * njp + 1][0] - mnew0);
            float p11 = __expf(sacc[2 * njp + 1][1] - mnew0);
            float p12 = __expf(sacc[2 * njp + 1][2] - mnew1);
            float p13 = __expf(sacc[2 * njp + 1][3] - mnew1);
            s0 += p00 + p01 + p10 + p11;
            s1 += p02 + p03 + p12 + p13;
            paf[njp][0] = h2_u32(__floats2half2_rn(p00, p01));
            paf[njp][1] = h2_u32(__floats2half2_rn(p02, p03));
            paf[njp][2] = h2_u32(__floats2half2_rn(p10, p11));
            paf[njp][3] = h2_u32(__floats2half2_rn(p12, p13));
        }
        #pragma unroll
        for (int off = 1; off <= 2; off <<= 1) {
            s0 += __shfl_xor_sync(0xffffffffu, s0, off);
            s1 += __shfl_xor_sync(0xffffffffu, s1, off);
        }
        lrow0 = lrow0 * alpha0 + s0;
        lrow1 = lrow1 * alpha1 + s1;

        // ---- rescale O, then O += P V ----
        #pragma unroll
        for (int i = 0; i < 16; i++) {
            oacc[i][0] *= alpha0; oacc[i][1] *= alpha0;
            oacc[i][2] *= alpha1; oacc[i][3] *= alpha1;
        }
        #pragma unroll
        for (int njp2 = 0; njp2 < 8; njp2++) {
            #pragma unroll
            for (int kf2 = 0; kf2 < 4; kf2++) {
                uint32_t bf[4];
                LDSM4(bf, vb + vfrag_off + njp2 * (16 * FV_ROWB) + kf2 * 32);
                mma16816(oacc[2 * njp2 + 0], paf[kf2], &bf[0]);
                mma16816(oacc[2 * njp2 + 1], paf[kf2], &bf[2]);
            }
        }
        __syncthreads();   // all warps done with this buffer before overwrite
    }

    // ---- write O / l ----
    float inv0 = 1.0f / lrow0;
    float inv1 = 1.0f / lrow1;
    int r0 = q0 + w * 16 + (lane >> 2);
    int cb = h * DH + (lane & 3) * 2;
    #pragma unroll
    for (int njo = 0; njo < 16; njo++) {
        int col = cb + njo * 8;
        *(__half2*)(g_cath + (size_t)r0 * CAT_K + col) =
            __floats2half2_rn(oacc[njo][0] * inv0, oacc[njo][1] * inv0);
        *(__half2*)(g_cath + (size_t)(r0 + 8) * CAT_K + col) =
            __floats2half2_rn(oacc[njo][2] * inv1, oacc[njo][3] * inv1);
    }
}

// --------------------------- SwiGLU activation ------------------------------
__global__ __launch_bounds__(256) void ff_act_kernel(void) {
    int row = blockIdx.y;
    int j2 = blockIdx.x * 256 + threadIdx.x;     // half2 index 0..4095
    const __half2* prow = (const __half2*)(g_projh + (size_t)row * FUSED_OUT);
    float2 xf = __half22float2(prow[FF_BASE / 2 + j2]);
    float2 gf = __half22float2(prow[GATE_BASE / 2 + j2]);
    float o0 = xf.x * (gf.x / (1.0f + expf(-gf.x)));
    float o1 = xf.y * (gf.y / (1.0f + expf(-gf.y)));
    ((__half2*)(g_cath + (size_t)row * CAT_K + ATTN_INNER))[j2] = __floats2half2_rn(o0, o1);
}

// ------------------------------- launch -------------------------------------
extern "C" void kernel_launch(void* const* d_in, const int* in_sizes, int n_in,
                              void* d_out, int out_size) {
    const float* x          = (const float*)d_in[0];
    const float* gamma      = (const float*)d_in[1];
    const float* w_fused    = (const float*)d_in[2];
    const float* w_attn_out = (const float*)d_in[3];
    const float* w_ff_out   = (const float*)d_in[4];
    float* out = (float*)d_out;

    __half *p_xnh, *p_projh, *p_cath, *p_wft, *p_wcatt;
    cudaGetSymbolAddress((void**)&p_xnh, g_xnh);
    cudaGetSymbolAddress((void**)&p_projh, g_projh);
    cudaGetSymbolAddress((void**)&p_cath, g_cath);
    cudaGetSymbolAddress((void**)&p_wft, g_wft);
    cudaGetSymbolAddress((void**)&p_wcatt, g_wcatt);

    const int SMEM_DYN = NSTG * STAGE;   // 221184 B
    cudaFuncSetAttribute((const void*)mma_gemm<true>,
                         cudaFuncAttributeMaxDynamicSharedMemorySize, SMEM_DYN);
    cudaFuncSetAttribute((const void*)mma_gemm<false>,
                         cudaFuncAttributeMaxDynamicSharedMemorySize, SMEM_DYN);
    cudaFuncSetAttribute((const void*)flash_attn,
                         cudaFuncAttributeMaxDynamicSharedMemorySize, FSMEM);

    // 0. weight convert+transpose to [N][K] half
    wtrans_kernel<<<dim3(FUSED_OUT / 32, DIM / 32), 256>>>(
        w_fused, FUSED_OUT, p_wft, DIM, 0);
    wtrans_kernel<<<dim3(DIM / 32, ATTN_INNER / 32), 256>>>(
        w_attn_out, DIM, p_wcatt, CAT_K, 0);
    wtrans_kernel<<<dim3(DIM / 32, FF_INNER / 32), 256>>>(
        w_ff_out, DIM, p_wcatt, CAT_K, ATTN_INNER);

    // 1. LayerNorm -> xn half
    ln_kernel<<<NSEQ, 256>>>(x, gamma);

    // 2. proj = xn @ wf^T  -> proj half
    mma_gemm<true>
        <<<dim3(NSEQ / 256, FUSED_OUT / 128, 1), 256, SMEM_DYN>>>(
        p_xnh, DIM, p_wft, DIM, p_projh, FUSED_OUT, DIM);

    // 2b. V transpose -> vt [DH][NSEQ] half
    vtrans_kernel<<<dim3(NSEQ / 32, DH / 32), 256>>>();

    // 3-5. fused flash attention -> cat cols [0,2048)
    flash_attn<<<dim3(NSEQ / 64, HEADS), 128, FSMEM>>>();

    // 6. SwiGLU -> cat cols [2048, 10240)
    ff_act_kernel<<<dim3(FF_INNER / 512, NSEQ), 256>>>();

    // 7. out = cat @ wcat^T  (fp32 out)
    mma_gemm<false>
        <<<dim3(NSEQ / 256, DIM / 128, 1), 256, SMEM_DYN>>>(
        p_cath, CAT_K, p_wcatt, CAT_K, out, DIM, CAT_K);
}

// round 14
// speedup vs baseline: 3.0478x; 1.0317x over previous
#include <cuda_runtime.h>
#include <cuda_fp16.h>
#include <cstdint>
#include <math.h>

// ---------------------------------------------------------------------------
// ParallelTransformerBlock, fp16 tensor-core path (mma.sync m16n8k16 + ldmatrix
// + cp.async). fp32 accumulate everywhere.
// R14: vectorized weight transpose (float4 loads / half4 stores) + vectorized
//      SwiGLU. Compute kernels identical to R13.
// ---------------------------------------------------------------------------

#define NSEQ 2048
#define DIM 2048
#define DH 128
#define HEADS 16
#define ATTN_INNER 2048
#define FF_INNER 8192
#define FUSED_OUT 18688
#define FF_BASE 2304      // ATTN_INNER + 2*DH
#define GATE_BASE 10496   // FF_BASE + FF_INNER
#define CAT_K (ATTN_INNER + FF_INNER)   // 10240
#define LN_EPS 1e-5f

// ------------------------- device scratch (static) -------------------------
__device__ __half g_xnh[(size_t)NSEQ * DIM];                    // 8 MB
__device__ __half g_projh[(size_t)NSEQ * FUSED_OUT];            // 76.5 MB
__device__ __half g_cath[(size_t)NSEQ * CAT_K];                 // 40 MB
__device__ __half g_vt[(size_t)DH * NSEQ];                      // 0.5 MB
__device__ __half g_wft[(size_t)FUSED_OUT * DIM];               // 76.5 MB  [N][K]
__device__ __half g_wcatt[(size_t)DIM * CAT_K];                 // 40 MB    [2048][10240]

// --------------------------- PTX helpers -----------------------------------
__device__ __forceinline__ uint32_t smem_u32(const void* p) {
    uint32_t a;
    asm("{ .reg .u64 t; cvta.to.shared.u64 t, %1; cvt.u32.u64 %0, t; }"
        : "=r"(a) : "l"(p));
    return a;
}

__device__ __forceinline__ uint32_t h2_u32(__half2 h) {
    union { __half2 h; uint32_t u; } cvt;
    cvt.h = h;
    return cvt.u;
}

#define CP_ASYNC16(smaddr, gptr) \
    asm volatile("cp.async.cg.shared.global [%0], [%1], 16;" :: "r"(smaddr), "l"(gptr))
#define CP_COMMIT() asm volatile("cp.async.commit_group;" ::: "memory")
#define CP_WAIT0()  asm volatile("cp.async.wait_group 0;" ::: "memory")
#define CP_WAIT1()  asm volatile("cp.async.wait_group 1;" ::: "memory")
#define CP_WAIT2()  asm volatile("cp.async.wait_group 2;" ::: "memory")

#define LDSM4(r, addr) \
    asm volatile("ldmatrix.sync.aligned.m8n8.x4.shared.b16 {%0,%1,%2,%3}, [%4];" \
                 : "=r"((r)[0]), "=r"((r)[1]), "=r"((r)[2]), "=r"((r)[3]) \
                 : "r"(addr))

__device__ __forceinline__ void mma16816(float* d, const uint32_t* a, const uint32_t* b) {
    asm volatile(
        "mma.sync.aligned.m16n8k16.row.col.f32.f16.f16.f32 "
        "{%0,%1,%2,%3}, {%4,%5,%6,%7}, {%8,%9}, {%0,%1,%2,%3};"
        : "+f"(d[0]), "+f"(d[1]), "+f"(d[2]), "+f"(d[3])
        : "r"(a[0]), "r"(a[1]), "r"(a[2]), "r"(a[3]), "r"(b[0]), "r"(b[1]));
}

// ------------------------------ LayerNorm ----------------------------------
__global__ __launch_bounds__(256) void ln_kernel(const float* __restrict__ x,
                                                 const float* __restrict__ gamma) {
    int row = blockIdx.x;
    int tid = threadIdx.x;
    const float4* xr = (const float4*)(x + (size_t)row * DIM);
    __half2* out = (__half2*)(g_xnh + (size_t)row * DIM);
    const float4* g4 = (const float4*)gamma;

    float s = 0.f, sq = 0.f;
    float4 v[2];
    #pragma unroll
    for (int i = 0; i < 2; i++) {
        v[i] = xr[tid + 256 * i];
        s += v[i].x + v[i].y + v[i].z + v[i].w;
        sq += v[i].x * v[i].x + v[i].y * v[i].y + v[i].z * v[i].z + v[i].w * v[i].w;
    }
    __shared__ float red[256], red2[256];
    red[tid] = s; red2[tid] = sq;
    __syncthreads();
    for (int off = 128; off > 0; off >>= 1) {
        if (tid < off) { red[tid] += red[tid + off]; red2[tid] += red2[tid + off]; }
        __syncthreads();
    }
    float mu = red[0] * (1.0f / DIM);
    float var = red2[0] * (1.0f / DIM) - mu * mu;
    float inv = rsqrtf(var + LN_EPS);
    #pragma unroll
    for (int i = 0; i < 2; i++) {
        float4 g = g4[tid + 256 * i];
        float a0 = (v[i].x - mu) * inv * g.x;
        float a1 = (v[i].y - mu) * inv * g.y;
        float a2 = (v[i].z - mu) * inv * g.z;
        float a3 = (v[i].w - mu) * inv * g.w;
        out[(tid + 256 * i) * 2 + 0] = __floats2half2_rn(a0, a1);
        out[(tid + 256 * i) * 2 + 1] = __floats2half2_rn(a2, a3);
    }
}

// --------- weight transpose + fp16 convert: [K,N] fp32 -> [N,K] half --------
// 64x64 tile; float4 global loads, fp32 smem (stride 65, <=2-way conflicts),
// uint2 (4-half) global stores -> 128B/warp coalesced both directions.
__global__ __launch_bounds__(256) void wtrans_kernel(const float* __restrict__ src,
                                                     int N, __half* __restrict__ dst,
                                                     long long ldd, long long koff) {
    __shared__ float tile[64][65];
    int n0 = blockIdx.x * 64;
    int k0 = blockIdx.y * 64;
    int tid = threadIdx.x;
    {
        int r = tid >> 4;          // 0..15 (k rows, x4)
        int c4 = tid & 15;         // float4 column
        #pragma unroll
        for (int i = 0; i < 4; i++) {
            int row = r + 16 * i;
            float4 v = *(const float4*)(src + (size_t)(k0 + row) * N + n0 + c4 * 4);
            tile[row][c4 * 4 + 0] = v.x;
            tile[row][c4 * 4 + 1] = v.y;
            tile[row][c4 * 4 + 2] = v.z;
            tile[row][c4 * 4 + 3] = v.w;
        }
    }
    __syncthreads();
    {
        int kc = tid & 15;         // 4-half chunk along k
        int nb = tid >> 4;         // 0..15 (n rows, x4)
        #pragma unroll
        for (int i = 0; i < 4; i++) {
            int nrow = nb + 16 * i;
            __half2 a = __floats2half2_rn(tile[kc * 4 + 0][nrow], tile[kc * 4 + 1][nrow]);
            __half2 b = __floats2half2_rn(tile[kc * 4 + 2][nrow], tile[kc * 4 + 3][nrow]);
            uint2 val;
            val.x = h2_u32(a);
            val.y = h2_u32(b);
            *(uint2*)(dst + (size_t)(n0 + nrow) * ldd + koff + k0 + kc * 4) = val;
        }
    }
}

// ---------------- V transpose (half->half): proj cols -> [DH][NSEQ] ---------
__global__ __launch_bounds__(256) void vtrans_kernel(void) {
    __shared__ __half tile[32][33];
    int s0 = blockIdx.x * 32;
    int d0 = blockIdx.y * 32;
    int tx = threadIdx.x & 31, ty = threadIdx.x >> 5;
    #pragma unroll
    for (int i = 0; i < 4; i++)
        tile[ty + 8 * i][tx] =
            g_projh[(size_t)(s0 + ty + 8 * i) * FUSED_OUT + ATTN_INNER + DH + d0 + tx];
    __syncthreads();
    #pragma unroll
    for (int i = 0; i < 4; i++)
        g_vt[(size_t)(d0 + ty + 8 * i) * NSEQ + s0 + tx] = tile[tx][ty + 8 * i];
}

// ------------------------- fp16 tensor-core GEMM ----------------------------
// C[M,N] = A[M,K] @ B^T, A half [M][K] k-contig, B half [N][K] k-contig.
// 256x128x64 CTA tile, 4-stage cp.async, 256 threads: 8 warps 4(m) x 2(n).
#define ROWB   144                      // bytes per smem row (64 halves + 8 pad)
#define ABYTES (256 * ROWB)             // 36864
#define BBYTES (128 * ROWB)             // 18432
#define STAGE  (ABYTES + BBYTES)        // 55296
#define NSTG   4

template <bool CHALF>
__global__ __launch_bounds__(256, 1)
void mma_gemm(const __half* __restrict__ A, long long lda,
              const __half* __restrict__ B, long long ldb,
              void* __restrict__ Cv, long long ldc,
              int K)
{
    const int bx = blockIdx.x;   // m tile
    const int by = blockIdx.y;   // n tile

    const int m0 = bx * 256;
    const int n0 = by * 128;
    const int NT = K >> 6;

    extern __shared__ char smem[];
    const uint32_t sm_u = smem_u32(smem);

    const int tid = threadIdx.x;
    const int lane = tid & 31;
    const int warp = tid >> 5;
    const int wm = warp & 3;
    const int wn = warp >> 2;
    const int g = lane >> 2;
    const int tig = lane & 3;

    const uint32_t a_off = (uint32_t)((wm * 64 + (lane & 15)) * ROWB + ((lane >> 4) << 4));
    const uint32_t b_off = (uint32_t)(ABYTES +
        (wn * 64 + (lane & 7) + ((lane >> 4) << 3)) * ROWB + (((lane >> 3) & 1) << 4));

    float acc[4][8][4];
    #pragma unroll
    for (int i = 0; i < 4; i++)
        #pragma unroll
        for (int j = 0; j < 8; j++)
            #pragma unroll
            for (int r = 0; r < 4; r++) acc[i][j][r] = 0.f;

    auto load_stage = [&](int st, int t) {
        const uint32_t abase = sm_u + st * STAGE;
        const uint32_t bbase = abase + ABYTES;
        const long long kk = (long long)t << 6;
        #pragma unroll
        for (int i = 0; i < 8; i++) {
            int idx = tid + 256 * i;
            int row = idx >> 3, seg = idx & 7;
            uint32_t so = abase + (uint32_t)(row * ROWB + seg * 16);
            const __half* gp = A + (size_t)(m0 + row) * lda + kk + seg * 8;
            CP_ASYNC16(so, gp);
        }
        #pragma unroll
        for (int i = 0; i < 4; i++) {
            int idx = tid + 256 * i;
            int row = idx >> 3, seg = idx & 7;
            uint32_t so = bbase + (uint32_t)(row * ROWB + seg * 16);
            const __half* gp = B + (size_t)(n0 + row) * ldb + kk + seg * 8;
            CP_ASYNC16(so, gp);
        }
    };

    #pragma unroll
    for (int s = 0; s < NSTG - 1; s++) {
        if (s < NT) load_stage(s, s);
        CP_COMMIT();
    }
    CP_WAIT2();
    __syncthreads();

    int st = 0;
    for (int t = 0; t < NT; t++) {
        int lt = t + NSTG - 1;
        int lst = st + NSTG - 1; if (lst >= NSTG) lst -= NSTG;
        if (lt < NT) load_stage(lst, lt);
        CP_COMMIT();

        const uint32_t abase = sm_u + st * STAGE;

        #pragma unroll
        for (int ks = 0; ks < 4; ks++) {
            uint32_t af[4][4], bf[4][4];
            #pragma unroll
            for (int mi = 0; mi < 4; mi++)
                LDSM4(af[mi], abase + a_off + mi * (16 * ROWB) + ks * 32);
            #pragma unroll
            for (int njp = 0; njp < 4; njp++)
                LDSM4(bf[njp], abase + b_off + njp * (16 * ROWB) + ks * 32);
            #pragma unroll
            for (int mi = 0; mi < 4; mi++)
                #pragma unroll
                for (int njp = 0; njp < 4; njp++) {
                    mma16816(acc[mi][2 * njp + 0], af[mi], &bf[njp][0]);
                    mma16816(acc[mi][2 * njp + 1], af[mi], &bf[njp][2]);
                }
        }
        CP_WAIT2();
        __syncthreads();
        if (++st == NSTG) st = 0;
    }

    #pragma unroll
    for (int mi = 0; mi < 4; mi++) {
        #pragma unroll
        for (int nj = 0; nj < 8; nj++) {
            int row = m0 + wm * 64 + mi * 16 + g;
            int col = n0 + wn * 64 + nj * 8 + tig * 2;
            if (CHALF) {
                __half* C = (__half*)Cv;
                *(__half2*)(C + (size_t)row * ldc + col) =
                    __floats2half2_rn(acc[mi][nj][0], acc[mi][nj][1]);
                *(__half2*)(C + (size_t)(row + 8) * ldc + col) =
                    __floats2half2_rn(acc[mi][nj][2], acc[mi][nj][3]);
            } else {
                float* C = (float*)Cv;
                *(float2*)(C + (size_t)row * ldc + col) =
                    make_float2(acc[mi][nj][0], acc[mi][nj][1]);
                *(float2*)(C + (size_t)(row + 8) * ldc + col) =
                    make_float2(acc[mi][nj][2], acc[mi][nj][3]);
            }
        }
    }
}

// ------------------------- fused flash attention -----------------------------
// grid (32 qblocks, 16 heads), 128 threads (4 warps, 16 q-rows each).
#define FQ_ROWB 272                     // Q/K smem row: 128 halves + 8 pad
#define FV_ROWB 144                     // Vt smem row: 64 halves + 8 pad
#define FQ_BYTES (64 * FQ_ROWB)         // 17408
#define FK_BYTES (64 * FQ_ROWB)         // 17408
#define FV_BYTES (128 * FV_ROWB)        // 18432
#define FSTAGE   (FK_BYTES + FV_BYTES)  // 35840
#define FSMEM    (FQ_BYTES + 2 * FSTAGE)// 89088

__global__ __launch_bounds__(128, 2)
void flash_attn(void) {
    const int qb = gridDim.x - 1 - blockIdx.x;      // big workloads first
    const int h = blockIdx.y;
    const int q0 = qb * 64;
    const int jmax = qb;                             // k-blocks 0..qb

    extern __shared__ char smem[];
    const uint32_t sm_u = smem_u32(smem);
    const uint32_t kbase0 = sm_u + FQ_BYTES;

    const int tid = threadIdx.x;
    const int lane = tid & 31;
    const int w = tid >> 5;

    const __half* Qg = g_projh + (size_t)h * DH;                 // row stride FUSED_OUT
    const __half* Kg = g_projh + ATTN_INNER;
    const __half* Vtg = g_vt;

    // ---- load + pre-scale Q into smem ----
    {
        const float scale = 0.08838834764831845f;
        for (int i = tid; i < 64 * 64; i += 128) {   // half2 granularity
            int row = i >> 6, c2 = i & 63;
            __half2 qv = *(const __half2*)(Qg + (size_t)(q0 + row) * FUSED_OUT + c2 * 2);
            float2 f = __half22float2(qv);
            *(__half2*)(smem + row * FQ_ROWB + c2 * 4) =
                __floats2half2_rn(f.x * scale, f.y * scale);
        }
    }

    // ---- stage loader ----
    auto load_stage = [&](int buf, int j) {
        const uint32_t kb = kbase0 + buf * FSTAGE;
        const uint32_t vb = kb + FK_BYTES;
        const int kp0 = j * 64;
        #pragma unroll
        for (int i = 0; i < 8; i++) {                // K: 64 rows x 256B
            int idx = tid + 128 * i;
            int row = idx >> 4, seg = idx & 15;
            CP_ASYNC16(kb + (uint32_t)(row * FQ_ROWB + seg * 16),
                       Kg + (size_t)(kp0 + row) * FUSED_OUT + seg * 8);
        }
        #pragma unroll
        for (int i = 0; i < 8; i++) {                // Vt: 128 rows x 128B
            int idx = tid + 128 * i;
            int row = idx >> 3, seg = idx & 7;
            CP_ASYNC16(vb + (uint32_t)(row * FV_ROWB + seg * 16),
                       Vtg + (size_t)row * NSEQ + kp0 + seg * 8);
        }
    };

    load_stage(0, 0);
    CP_COMMIT();
    __syncthreads();    // Q smem ready

    // ---- Q fragments (pre-scaled) ----
    uint32_t qf[8][4];
    {
        const uint32_t qoff = (uint32_t)((w * 16 + (lane & 15)) * FQ_ROWB + ((lane >> 4) << 4));
        #pragma unroll
        for (int kf = 0; kf < 8; kf++)
            LDSM4(qf[kf], sm_u + qoff + kf * 32);
    }

    // ---- state ----
    float oacc[16][4];
    #pragma unroll
    for (int i = 0; i < 16; i++)
        #pragma unroll
        for (int r = 0; r < 4; r++) oacc[i][r] = 0.f;
    float mrow0 = -INFINITY, mrow1 = -INFINITY;
    float lrow0 = 0.f, lrow1 = 0.f;

    const uint32_t kfrag_off = (uint32_t)(((lane & 7) + ((lane >> 4) << 3)) * FQ_ROWB +
                                          (((lane >> 3) & 1) << 4));
    const uint32_t vfrag_off = (uint32_t)(((lane & 7) + ((lane >> 4) << 3)) * FV_ROWB +
                                          (((lane >> 3) & 1) << 4));

    for (int j = 0; j <= jmax; j++) {
        int buf = j & 1;
        if (j < jmax) { load_stage(buf ^ 1, j + 1); CP_COMMIT(); }
        if (j < jmax) { CP_WAIT1(); } else { CP_WAIT0(); }
        __syncthreads();

        const uint32_t kb = kbase0 + buf * FSTAGE;
        const uint32_t vb = kb + FK_BYTES;

        // ---- S = Q K^T ----
        float sacc[8][4];
        #pragma unroll
        for (int nj = 0; nj < 8; nj++)
            #pragma unroll
            for (int r = 0; r < 4; r++) sacc[nj][r] = 0.f;
        #pragma unroll
        for (int njp = 0; njp < 4; njp++) {
            #pragma unroll
            for (int kf = 0; kf < 8; kf++) {
                uint32_t bf[4];
                LDSM4(bf, kb + kfrag_off + njp * (16 * FQ_ROWB) + kf * 32);
                mma16816(sacc[2 * njp + 0], qf[kf], &bf[0]);
                mma16816(sacc[2 * njp + 1], qf[kf], &bf[2]);
            }
        }

        // ---- causal mask on diagonal block ----
        if (j == jmax) {
            int r0 = q0 + w * 16 + (lane >> 2);
            int cb = j * 64 + (lane & 3) * 2;
            #pragma unroll
            for (int nj = 0; nj < 8; nj++) {
                int c = cb + nj * 8;
                if (c > r0)     sacc[nj][0] = -1e30f;
                if (c + 1 > r0) sacc[nj][1] = -1e30f;
                if (c > r0 + 8)     sacc[nj][2] = -1e30f;
                if (c + 1 > r0 + 8) sacc[nj][3] = -1e30f;
            }
        }

        // ---- online softmax ----
        float bm0 = sacc[0][0], bm1 = sacc[0][2];
        #pragma unroll
        for (int nj = 0; nj < 8; nj++) {
            bm0 = fmaxf(bm0, fmaxf(sacc[nj][0], sacc[nj][1]));
            bm1 = fmaxf(bm1, fmaxf(sacc[nj][2], sacc[nj][3]));
        }
        #pragma unroll
        for (int off = 1; off <= 2; off <<= 1) {
            bm0 = fmaxf(bm0, __shfl_xor_sync(0xffffffffu, bm0, off));
            bm1 = fmaxf(bm1, __shfl_xor_sync(0xffffffffu, bm1, off));
        }
        float mnew0 = fmaxf(mrow0, bm0);
        float mnew1 = fmaxf(mrow1, bm1);
        float alpha0 = __expf(mrow0 - mnew0);
        float alpha1 = __expf(mrow1 - mnew1);
        mrow0 = mnew0; mrow1 = mnew1;

        uint32_t paf[4][4];
        float s0 = 0.f, s1 = 0.f;
        #pragma unroll
        for (int njp = 0; njp < 4; njp++) {
            float p00 = __expf(sacc[2 * njp + 0][0] - mnew0);
            float p01 = __expf(sacc[2 * njp + 0][1] - mnew0);
            float p02 = __expf(sacc[2 * njp + 0][2] - mnew1);
            float p03 = __expf(sacc[2 * njp + 0][3] - mnew1);
            float p10 = __expf(sacc[2 * njp + 1][0] - mnew0);
            float p11 = __expf(sacc[2 * njp + 1][1] - mnew0);
            float p12 = __expf(sacc[2 * njp + 1][2] - mnew1);
            float p13 = __expf(sacc[2 * njp + 1][3] - mnew1);
            s0 += p00 + p01 + p10 + p11;
            s1 += p02 + p03 + p12 + p13;
            paf[njp][0] = h2_u32(__floats2half2_rn(p00, p01));
            paf[njp][1] = h2_u32(__floats2half2_rn(p02, p03));
            paf[njp][2] = h2_u32(__floats2half2_rn(p10, p11));
            paf[njp][3] = h2_u32(__floats2half2_rn(p12, p13));
        }
        #pragma unroll
        for (int off = 1; off <= 2; off <<= 1) {
            s0 += __shfl_xor_sync(0xffffffffu, s0, off);
            s1 += __shfl_xor_sync(0xffffffffu, s1, off);
        }
        lrow0 = lrow0 * alpha0 + s0;
        lrow1 = lrow1 * alpha1 + s1;

        // ---- rescale O, then O += P V ----
        #pragma unroll
        for (int i = 0; i < 16; i++) {
            oacc[i][0] *= alpha0; oacc[i][1] *= alpha0;
            oacc[i][2] *= alpha1; oacc[i][3] *= alpha1;
        }
        #pragma unroll
        for (int njp2 = 0; njp2 < 8; njp2++) {
            #pragma unroll
            for (int kf2 = 0; kf2 < 4; kf2++) {
                uint32_t bf[4];
                LDSM4(bf, vb + vfrag_off + njp2 * (16 * FV_ROWB) + kf2 * 32);
                mma16816(oacc[2 * njp2 + 0], paf[kf2], &bf[0]);
                mma16816(oacc[2 * njp2 + 1], paf[kf2], &bf[2]);
            }
        }
        __syncthreads();   // all warps done with this buffer before overwrite
    }

    // ---- write O / l ----
    float inv0 = 1.0f / lrow0;
    float inv1 = 1.0f / lrow1;
    int r0 = q0 + w * 16 + (lane >> 2);
    int cb = h * DH + (lane & 3) * 2;
    #pragma unroll
    for (int njo = 0; njo < 16; njo++) {
        int col = cb + njo * 8;
        *(__half2*)(g_cath + (size_t)r0 * CAT_K + col) =
            __floats2half2_rn(oacc[njo][0] * inv0, oacc[njo][1] * inv0);
        *(__half2*)(g_cath + (size_t)(r0 + 8) * CAT_K + col) =
            __floats2half2_rn(oacc[njo][2] * inv1, oacc[njo][3] * inv1);
    }
}

// --------------------------- SwiGLU activation ------------------------------
// proj half -> cat half cols [2048, 10240); uint4 (8 halves) per thread.
__global__ __launch_bounds__(256) void ff_act_kernel(void) {
    int row = blockIdx.y;
    int j8 = blockIdx.x * 256 + threadIdx.x;     // 8-half chunk index 0..1023
    const __half* prow = g_projh + (size_t)row * FUSED_OUT;
    uint4 xv = *(const uint4*)(prow + FF_BASE + j8 * 8);
    uint4 gv = *(const uint4*)(prow + GATE_BASE + j8 * 8);
    const uint32_t* xp = (const uint32_t*)&xv;
    const uint32_t* gp = (const uint32_t*)&gv;
    uint4 ov;
    uint32_t* op = (uint32_t*)&ov;
    #pragma unroll
    for (int k = 0; k < 4; k++) {
        union { uint32_t u; __half2 h; } xu, gu;
        xu.u = xp[k]; gu.u = gp[k];
        float2 xf = __half22float2(xu.h);
        float2 gf = __half22float2(gu.h);
        float o0 = xf.x * (gf.x / (1.0f + __expf(-gf.x)));
        float o1 = xf.y * (gf.y / (1.0f + __expf(-gf.y)));
        op[k] = h2_u32(__floats2half2_rn(o0, o1));
    }
    *(uint4*)(g_cath + (size_t)row * CAT_K + ATTN_INNER + j8 * 8) = ov;
}

// ------------------------------- launch -------------------------------------
extern "C" void kernel_launch(void* const* d_in, const int* in_sizes, int n_in,
                              void* d_out, int out_size) {
    const float* x          = (const float*)d_in[0];
    const float* gamma      = (const float*)d_in[1];
    const float* w_fused    = (const float*)d_in[2];
    const float* w_attn_out = (const float*)d_in[3];
    const float* w_ff_out   = (const float*)d_in[4];
    float* out = (float*)d_out;

    __half *p_xnh, *p_projh, *p_cath, *p_wft, *p_wcatt;
    cudaGetSymbolAddress((void**)&p_xnh, g_xnh);
    cudaGetSymbolAddress((void**)&p_projh, g_projh);
    cudaGetSymbolAddress((void**)&p_cath, g_cath);
    cudaGetSymbolAddress((void**)&p_wft, g_wft);
    cudaGetSymbolAddress((void**)&p_wcatt, g_wcatt);

    const int SMEM_DYN = NSTG * STAGE;   // 221184 B
    cudaFuncSetAttribute((const void*)mma_gemm<true>,
                         cudaFuncAttributeMaxDynamicSharedMemorySize, SMEM_DYN);
    cudaFuncSetAttribute((const void*)mma_gemm<false>,
                         cudaFuncAttributeMaxDynamicSharedMemorySize, SMEM_DYN);
    cudaFuncSetAttribute((const void*)flash_attn,
                         cudaFuncAttributeMaxDynamicSharedMemorySize, FSMEM);

    // 0. weight convert+transpose to [N][K] half (vectorized 64x64 tiles)
    wtrans_kernel<<<dim3(FUSED_OUT / 64, DIM / 64), 256>>>(
        w_fused, FUSED_OUT, p_wft, DIM, 0);
    wtrans_kernel<<<dim3(DIM / 64, ATTN_INNER / 64), 256>>>(
        w_attn_out, DIM, p_wcatt, CAT_K, 0);
    wtrans_kernel<<<dim3(DIM / 64, FF_INNER / 64), 256>>>(
        w_ff_out, DIM, p_wcatt, CAT_K, ATTN_INNER);

    // 1. LayerNorm -> xn half
    ln_kernel<<<NSEQ, 256>>>(x, gamma);

    // 2. proj = xn @ wf^T  -> proj half
    mma_gemm<true>
        <<<dim3(NSEQ / 256, FUSED_OUT / 128, 1), 256, SMEM_DYN>>>(
        p_xnh, DIM, p_wft, DIM, p_projh, FUSED_OUT, DIM);

    // 2b. V transpose -> vt [DH][NSEQ] half
    vtrans_kernel<<<dim3(NSEQ / 32, DH / 32), 256>>>();

    // 3-5. fused flash attention -> cat cols [0,2048)
    flash_attn<<<dim3(NSEQ / 64, HEADS), 128, FSMEM>>>();

    // 6. SwiGLU -> cat cols [2048, 10240)
    ff_act_kernel<<<dim3(FF_INNER / 2048, NSEQ), 256>>>();

    // 7. out = cat @ wcat^T  (fp32 out)
    mma_gemm<false>
        <<<dim3(NSEQ / 256, DIM / 128, 1), 256, SMEM_DYN>>>(
        p_cath, CAT_K, p_wcatt, CAT_K, out, DIM, CAT_K);
}

// round 15
// speedup vs baseline: 3.0569x; 1.0030x over previous
#include <cuda_runtime.h>
#include <cuda_fp16.h>
#include <cstdint>
#include <math.h>

// ---------------------------------------------------------------------------
// ParallelTransformerBlock, fp16 tensor-core path (mma.sync m16n8k16 + ldmatrix
// + cp.async). fp32 accumulate everywhere.
// R15: B operands consumed via ldmatrix.trans from [K][N] layout ->
//      weight prep is a pure streaming convert (no transpose); vtrans deleted
//      (flash PV reads V directly from proj). Arithmetic identical to R14.
// ---------------------------------------------------------------------------

#define NSEQ 2048
#define DIM 2048
#define DH 128
#define HEADS 16
#define ATTN_INNER 2048
#define FF_INNER 8192
#define FUSED_OUT 18688
#define FF_BASE 2304      // ATTN_INNER + 2*DH
#define GATE_BASE 10496   // FF_BASE + FF_INNER
#define CAT_K (ATTN_INNER + FF_INNER)   // 10240
#define LN_EPS 1e-5f

// ------------------------- device scratch (static) -------------------------
__device__ __half g_xnh[(size_t)NSEQ * DIM];                    // 8 MB
__device__ __half g_projh[(size_t)NSEQ * FUSED_OUT];            // 76.5 MB
__device__ __half g_cath[(size_t)NSEQ * CAT_K];                 // 40 MB
__device__ __half g_wfh[(size_t)DIM * FUSED_OUT];               // 76.5 MB  [K][N]
__device__ __half g_wcath[(size_t)CAT_K * DIM];                 // 40 MB    [10240][2048]

// --------------------------- PTX helpers -----------------------------------
__device__ __forceinline__ uint32_t smem_u32(const void* p) {
    uint32_t a;
    asm("{ .reg .u64 t; cvta.to.shared.u64 t, %1; cvt.u32.u64 %0, t; }"
        : "=r"(a) : "l"(p));
    return a;
}

__device__ __forceinline__ uint32_t h2_u32(__half2 h) {
    union { __half2 h; uint32_t u; } cvt;
    cvt.h = h;
    return cvt.u;
}

#define CP_ASYNC16(smaddr, gptr) \
    asm volatile("cp.async.cg.shared.global [%0], [%1], 16;" :: "r"(smaddr), "l"(gptr))
#define CP_COMMIT() asm volatile("cp.async.commit_group;" ::: "memory")
#define CP_WAIT0()  asm volatile("cp.async.wait_group 0;" ::: "memory")
#define CP_WAIT1()  asm volatile("cp.async.wait_group 1;" ::: "memory")
#define CP_WAIT2()  asm volatile("cp.async.wait_group 2;" ::: "memory")

#define LDSM4(r, addr) \
    asm volatile("ldmatrix.sync.aligned.m8n8.x4.shared.b16 {%0,%1,%2,%3}, [%4];" \
                 : "=r"((r)[0]), "=r"((r)[1]), "=r"((r)[2]), "=r"((r)[3]) \
                 : "r"(addr))

#define LDSM4T(r, addr) \
    asm volatile("ldmatrix.sync.aligned.m8n8.x4.trans.shared.b16 {%0,%1,%2,%3}, [%4];" \
                 : "=r"((r)[0]), "=r"((r)[1]), "=r"((r)[2]), "=r"((r)[3]) \
                 : "r"(addr))

__device__ __forceinline__ void mma16816(float* d, const uint32_t* a, const uint32_t* b) {
    asm volatile(
        "mma.sync.aligned.m16n8k16.row.col.f32.f16.f16.f32 "
        "{%0,%1,%2,%3}, {%4,%5,%6,%7}, {%8,%9}, {%0,%1,%2,%3};"
        : "+f"(d[0]), "+f"(d[1]), "+f"(d[2]), "+f"(d[3])
        : "r"(a[0]), "r"(a[1]), "r"(a[2]), "r"(a[3]), "r"(b[0]), "r"(b[1]));
}

// ------------------------------ LayerNorm ----------------------------------
__global__ __launch_bounds__(256) void ln_kernel(const float* __restrict__ x,
                                                 const float* __restrict__ gamma) {
    int row = blockIdx.x;
    int tid = threadIdx.x;
    const float4* xr = (const float4*)(x + (size_t)row * DIM);
    __half2* out = (__half2*)(g_xnh + (size_t)row * DIM);
    const float4* g4 = (const float4*)gamma;

    float s = 0.f, sq = 0.f;
    float4 v[2];
    #pragma unroll
    for (int i = 0; i < 2; i++) {
        v[i] = xr[tid + 256 * i];
        s += v[i].x + v[i].y + v[i].z + v[i].w;
        sq += v[i].x * v[i].x + v[i].y * v[i].y + v[i].z * v[i].z + v[i].w * v[i].w;
    }
    __shared__ float red[256], red2[256];
    red[tid] = s; red2[tid] = sq;
    __syncthreads();
    for (int off = 128; off > 0; off >>= 1) {
        if (tid < off) { red[tid] += red[tid + off]; red2[tid] += red2[tid + off]; }
        __syncthreads();
    }
    float mu = red[0] * (1.0f / DIM);
    float var = red2[0] * (1.0f / DIM) - mu * mu;
    float inv = rsqrtf(var + LN_EPS);
    #pragma unroll
    for (int i = 0; i < 2; i++) {
        float4 g = g4[tid + 256 * i];
        float a0 = (v[i].x - mu) * inv * g.x;
        float a1 = (v[i].y - mu) * inv * g.y;
        float a2 = (v[i].z - mu) * inv * g.z;
        float a3 = (v[i].w - mu) * inv * g.w;
        out[(tid + 256 * i) * 2 + 0] = __floats2half2_rn(a0, a1);
        out[(tid + 256 * i) * 2 + 1] = __floats2half2_rn(a2, a3);
    }
}

// ----------------- weight fp32 -> fp16 streaming convert --------------------
// Pure copy (layout preserved): float4 x2 in, uint4 (8 halves) out.
__global__ __launch_bounds__(256) void wconv_kernel(const float* __restrict__ src,
                                                    __half* __restrict__ dst, size_t n) {
    size_t stride = (size_t)gridDim.x * 256 * 8;
    for (size_t i = ((size_t)blockIdx.x * 256 + threadIdx.x) * 8; i < n; i += stride) {
        float4 a = *(const float4*)(src + i);
        float4 b = *(const float4*)(src + i + 4);
        uint4 o;
        o.x = h2_u32(__floats2half2_rn(a.x, a.y));
        o.y = h2_u32(__floats2half2_rn(a.z, a.w));
        o.z = h2_u32(__floats2half2_rn(b.x, b.y));
        o.w = h2_u32(__floats2half2_rn(b.z, b.w));
        *(uint4*)(dst + i) = o;
    }
}

// ------------------------- fp16 tensor-core GEMM ----------------------------
// C[M,N] = A[M,K] @ B, A half [M][K] k-contig, B half [K][N] n-contig
// (consumed via ldmatrix.trans). 256x128x64 CTA tile, 4-stage cp.async,
// 256 threads: 8 warps 4(m) x 2(n), each warp 64x64.
#define ROWB   144                      // A smem row: 64 halves + 8 pad
#define BROWB  272                      // B smem row: 128 halves + 8 pad
#define ABYTES (256 * ROWB)             // 36864
#define BBYTES (64 * BROWB)             // 17408
#define STAGE  (ABYTES + BBYTES)        // 54272
#define NSTG   4

template <bool CHALF>
__global__ __launch_bounds__(256, 1)
void mma_gemm(const __half* __restrict__ A, long long lda,
              const __half* __restrict__ B, long long ldb,
              void* __restrict__ Cv, long long ldc,
              int K)
{
    const int bx = blockIdx.x;   // m tile
    const int by = blockIdx.y;   // n tile

    const int m0 = bx * 256;
    const int n0 = by * 128;
    const int NT = K >> 6;

    extern __shared__ char smem[];
    const uint32_t sm_u = smem_u32(smem);

    const int tid = threadIdx.x;
    const int lane = tid & 31;
    const int warp = tid >> 5;
    const int wm = warp & 3;
    const int wn = warp >> 2;
    const int g = lane >> 2;
    const int tig = lane & 3;

    const uint32_t a_off = (uint32_t)((wm * 64 + (lane & 15)) * ROWB + ((lane >> 4) << 4));
    // trans-B: row = k (lane&15), col offset = warp n-base + quadrant n-offset
    const uint32_t b_off = (uint32_t)(ABYTES +
        (lane & 15) * BROWB + wn * 128 + ((lane >> 4) << 4));

    float acc[4][8][4];
    #pragma unroll
    for (int i = 0; i < 4; i++)
        #pragma unroll
        for (int j = 0; j < 8; j++)
            #pragma unroll
            for (int r = 0; r < 4; r++) acc[i][j][r] = 0.f;

    auto load_stage = [&](int st, int t) {
        const uint32_t abase = sm_u + st * STAGE;
        const uint32_t bbase = abase + ABYTES;
        const long long kk = (long long)t << 6;
        #pragma unroll
        for (int i = 0; i < 8; i++) {              // A: 256 rows x 128B
            int idx = tid + 256 * i;
            int row = idx >> 3, seg = idx & 7;
            uint32_t so = abase + (uint32_t)(row * ROWB + seg * 16);
            const __half* gp = A + (size_t)(m0 + row) * lda + kk + seg * 8;
            CP_ASYNC16(so, gp);
        }
        #pragma unroll
        for (int i = 0; i < 4; i++) {              // B: 64 k-rows x 256B
            int idx = tid + 256 * i;
            int row = idx >> 4, seg = idx & 15;
            uint32_t so = bbase + (uint32_t)(row * BROWB + seg * 16);
            const __half* gp = B + (size_t)(kk + row) * ldb + n0 + seg * 8;
            CP_ASYNC16(so, gp);
        }
    };

    #pragma unroll
    for (int s = 0; s < NSTG - 1; s++) {
        if (s < NT) load_stage(s, s);
        CP_COMMIT();
    }
    CP_WAIT2();
    __syncthreads();

    int st = 0;
    for (int t = 0; t < NT; t++) {
        int lt = t + NSTG - 1;
        int lst = st + NSTG - 1; if (lst >= NSTG) lst -= NSTG;
        if (lt < NT) load_stage(lst, lt);
        CP_COMMIT();

        const uint32_t abase = sm_u + st * STAGE;

        #pragma unroll
        for (int ks = 0; ks < 4; ks++) {
            uint32_t af[4][4], bf[4][4];
            #pragma unroll
            for (int mi = 0; mi < 4; mi++)
                LDSM4(af[mi], abase + a_off + mi * (16 * ROWB) + ks * 32);
            #pragma unroll
            for (int njp = 0; njp < 4; njp++)
                LDSM4T(bf[njp], abase + b_off + njp * 32 + ks * (16 * BROWB));
            #pragma unroll
            for (int mi = 0; mi < 4; mi++)
                #pragma unroll
                for (int njp = 0; njp < 4; njp++) {
                    mma16816(acc[mi][2 * njp + 0], af[mi], &bf[njp][0]);
                    mma16816(acc[mi][2 * njp + 1], af[mi], &bf[njp][2]);
                }
        }
        CP_WAIT2();
        __syncthreads();
        if (++st == NSTG) st = 0;
    }

    #pragma unroll
    for (int mi = 0; mi < 4; mi++) {
        #pragma unroll
        for (int nj = 0; nj < 8; nj++) {
            int row = m0 + wm * 64 + mi * 16 + g;
            int col = n0 + wn * 64 + nj * 8 + tig * 2;
            if (CHALF) {
                __half* C = (__half*)Cv;
                *(__half2*)(C + (size_t)row * ldc + col) =
                    __floats2half2_rn(acc[mi][nj][0], acc[mi][nj][1]);
                *(__half2*)(C + (size_t)(row + 8) * ldc + col) =
                    __floats2half2_rn(acc[mi][nj][2], acc[mi][nj][3]);
            } else {
                float* C = (float*)Cv;
                *(float2*)(C + (size_t)row * ldc + col) =
                    make_float2(acc[mi][nj][0], acc[mi][nj][1]);
                *(float2*)(C + (size_t)(row + 8) * ldc + col) =
                    make_float2(acc[mi][nj][2], acc[mi][nj][3]);
            }
        }
    }
}

// ------------------------- fused flash attention -----------------------------
// grid (32 qblocks, 16 heads), 128 threads (4 warps, 16 q-rows each).
// K operand: proj K cols, [seq][dh] k-contig (non-trans ldmatrix).
// V operand: proj V cols, [seq][dh] = [K][N] (trans ldmatrix, no pre-transpose).
#define FQ_ROWB 272                     // 128 halves + 8 pad
#define FQ_BYTES (64 * FQ_ROWB)         // 17408
#define FK_BYTES (64 * FQ_ROWB)         // 17408
#define FV_BYTES (64 * FQ_ROWB)         // 17408
#define FSTAGE   (FK_BYTES + FV_BYTES)  // 34816
#define FSMEM    (FQ_BYTES + 2 * FSTAGE)// 87040

__global__ __launch_bounds__(128, 2)
void flash_attn(void) {
    const int qb = gridDim.x - 1 - blockIdx.x;      // big workloads first
    const int h = blockIdx.y;
    const int q0 = qb * 64;
    const int jmax = qb;                             // k-blocks 0..qb

    extern __shared__ char smem[];
    const uint32_t sm_u = smem_u32(smem);
    const uint32_t kbase0 = sm_u + FQ_BYTES;

    const int tid = threadIdx.x;
    const int lane = tid & 31;
    const int w = tid >> 5;

    const __half* Qg = g_projh + (size_t)h * DH;                 // row stride FUSED_OUT
    const __half* Kg = g_projh + ATTN_INNER;
    const __half* Vg = g_projh + ATTN_INNER + DH;

    // ---- load + pre-scale Q into smem ----
    {
        const float scale = 0.08838834764831845f;
        for (int i = tid; i < 64 * 64; i += 128) {   // half2 granularity
            int row = i >> 6, c2 = i & 63;
            __half2 qv = *(const __half2*)(Qg + (size_t)(q0 + row) * FUSED_OUT + c2 * 2);
            float2 f = __half22float2(qv);
            *(__half2*)(smem + row * FQ_ROWB + c2 * 4) =
                __floats2half2_rn(f.x * scale, f.y * scale);
        }
    }

    // ---- stage loader (K block + V block, both 64 seq-rows x 256B) ----
    auto load_stage = [&](int buf, int j) {
        const uint32_t kb = kbase0 + buf * FSTAGE;
        const uint32_t vb = kb + FK_BYTES;
        const int kp0 = j * 64;
        #pragma unroll
        for (int i = 0; i < 8; i++) {
            int idx = tid + 128 * i;
            int row = idx >> 4, seg = idx & 15;
            CP_ASYNC16(kb + (uint32_t)(row * FQ_ROWB + seg * 16),
                       Kg + (size_t)(kp0 + row) * FUSED_OUT + seg * 8);
        }
        #pragma unroll
        for (int i = 0; i < 8; i++) {
            int idx = tid + 128 * i;
            int row = idx >> 4, seg = idx & 15;
            CP_ASYNC16(vb + (uint32_t)(row * FQ_ROWB + seg * 16),
                       Vg + (size_t)(kp0 + row) * FUSED_OUT + seg * 8);
        }
    };

    load_stage(0, 0);
    CP_COMMIT();
    __syncthreads();    // Q smem ready

    // ---- Q fragments (pre-scaled) ----
    uint32_t qf[8][4];
    {
        const uint32_t qoff = (uint32_t)((w * 16 + (lane & 15)) * FQ_ROWB + ((lane >> 4) << 4));
        #pragma unroll
        for (int kf = 0; kf < 8; kf++)
            LDSM4(qf[kf], sm_u + qoff + kf * 32);
    }

    // ---- state ----
    float oacc[16][4];
    #pragma unroll
    for (int i = 0; i < 16; i++)
        #pragma unroll
        for (int r = 0; r < 4; r++) oacc[i][r] = 0.f;
    float mrow0 = -INFINITY, mrow1 = -INFINITY;
    float lrow0 = 0.f, lrow1 = 0.f;

    const uint32_t kfrag_off = (uint32_t)(((lane & 7) + ((lane >> 4) << 3)) * FQ_ROWB +
                                          (((lane >> 3) & 1) << 4));
    const uint32_t vfrag_off = (uint32_t)((lane & 15) * FQ_ROWB + ((lane >> 4) << 4));

    for (int j = 0; j <= jmax; j++) {
        int buf = j & 1;
        if (j < jmax) { load_stage(buf ^ 1, j + 1); CP_COMMIT(); }
        if (j < jmax) { CP_WAIT1(); } else { CP_WAIT0(); }
        __syncthreads();

        const uint32_t kb = kbase0 + buf * FSTAGE;
        const uint32_t vb = kb + FK_BYTES;

        // ---- S = Q K^T ----
        float sacc[8][4];
        #pragma unroll
        for (int nj = 0; nj < 8; nj++)
            #pragma unroll
            for (int r = 0; r < 4; r++) sacc[nj][r] = 0.f;
        #pragma unroll
        for (int njp = 0; njp < 4; njp++) {
            #pragma unroll
            for (int kf = 0; kf < 8; kf++) {
                uint32_t bf[4];
                LDSM4(bf, kb + kfrag_off + njp * (16 * FQ_ROWB) + kf * 32);
                mma16816(sacc[2 * njp + 0], qf[kf], &bf[0]);
                mma16816(sacc[2 * njp + 1], qf[kf], &bf[2]);
            }
        }

        // ---- causal mask on diagonal block ----
        if (j == jmax) {
            int r0 = q0 + w * 16 + (lane >> 2);
            int cb = j * 64 + (lane & 3) * 2;
            #pragma unroll
            for (int nj = 0; nj < 8; nj++) {
                int c = cb + nj * 8;
                if (c > r0)     sacc[nj][0] = -1e30f;
                if (c + 1 > r0) sacc[nj][1] = -1e30f;
                if (c > r0 + 8)     sacc[nj][2] = -1e30f;
                if (c + 1 > r0 + 8) sacc[nj][3] = -1e30f;
            }
        }

        // ---- online softmax ----
        float bm0 = sacc[0][0], bm1 = sacc[0][2];
        #pragma unroll
        for (int nj = 0; nj < 8; nj++) {
            bm0 = fmaxf(bm0, fmaxf(sacc[nj][0], sacc[nj][1]));
            bm1 = fmaxf(bm1, fmaxf(sacc[nj][2], sacc[nj][3]));
        }
        #pragma unroll
        for (int off = 1; off <= 2; off <<= 1) {
            bm0 = fmaxf(bm0, __shfl_xor_sync(0xffffffffu, bm0, off));
            bm1 = fmaxf(bm1, __shfl_xor_sync(0xffffffffu, bm1, off));
        }
        float mnew0 = fmaxf(mrow0, bm0);
        float mnew1 = fmaxf(mrow1, bm1);
        float alpha0 = __expf(mrow0 - mnew0);
        float alpha1 = __expf(mrow1 - mnew1);
        mrow0 = mnew0; mrow1 = mnew1;

        uint32_t paf[4][4];
        float s0 = 0.f, s1 = 0.f;
        #pragma unroll
        for (int njp = 0; njp < 4; njp++) {
            float p00 = __expf(sacc[2 * njp + 0][0] - mnew0);
            float p01 = __expf(sacc[2 * njp + 0][1] - mnew0);
            float p02 = __expf(sacc[2 * njp + 0][2] - mnew1);
            float p03 = __expf(sacc[2 * njp + 0][3] - mnew1);
            float p10 = __expf(sacc[2 * njp + 1][0] - mnew0);
            float p11 = __expf(sacc[2 * njp + 1][1] - mnew0);
            float p12 = __expf(sacc[2 * njp + 1][2] - mnew1);
            float p13 = __expf(sacc[2 * njp + 1][3] - mnew1);
            s0 += p00 + p01 + p10 + p11;
            s1 += p02 + p03 + p12 + p13;
            paf[njp][0] = h2_u32(__floats2half2_rn(p00, p01));
            paf[njp][1] = h2_u32(__floats2half2_rn(p02, p03));
            paf[njp][2] = h2_u32(__floats2half2_rn(p10, p11));
            paf[njp][3] = h2_u32(__floats2half2_rn(p12, p13));
        }
        #pragma unroll
        for (int off = 1; off <= 2; off <<= 1) {
            s0 += __shfl_xor_sync(0xffffffffu, s0, off);
            s1 += __shfl_xor_sync(0xffffffffu, s1, off);
        }
        lrow0 = lrow0 * alpha0 + s0;
        lrow1 = lrow1 * alpha1 + s1;

        // ---- rescale O, then O += P V (trans-ldmatrix from [seq][dh]) ----
        #pragma unroll
        for (int i = 0; i < 16; i++) {
            oacc[i][0] *= alpha0; oacc[i][1] *= alpha0;
            oacc[i][2] *= alpha1; oacc[i][3] *= alpha1;
        }
        #pragma unroll
        for (int njp2 = 0; njp2 < 8; njp2++) {
            #pragma unroll
            for (int kf2 = 0; kf2 < 4; kf2++) {
                uint32_t bf[4];
                LDSM4T(bf, vb + vfrag_off + njp2 * 32 + kf2 * (16 * FQ_ROWB));
                mma16816(oacc[2 * njp2 + 0], paf[kf2], &bf[0]);
                mma16816(oacc[2 * njp2 + 1], paf[kf2], &bf[2]);
            }
        }
        __syncthreads();   // all warps done with this buffer before overwrite
    }

    // ---- write O ----
    float inv0 = 1.0f / lrow0;
    float inv1 = 1.0f / lrow1;
    int r0 = q0 + w * 16 + (lane >> 2);
    int cb = h * DH + (lane & 3) * 2;
    #pragma unroll
    for (int njo = 0; njo < 16; njo++) {
        int col = cb + njo * 8;
        *(__half2*)(g_cath + (size_t)r0 * CAT_K + col) =
            __floats2half2_rn(oacc[njo][0] * inv0, oacc[njo][1] * inv0);
        *(__half2*)(g_cath + (size_t)(r0 + 8) * CAT_K + col) =
            __floats2half2_rn(oacc[njo][2] * inv1, oacc[njo][3] * inv1);
    }
}

// --------------------------- SwiGLU activation ------------------------------
// proj half -> cat half cols [2048, 10240); uint4 (8 halves) per thread.
__global__ __launch_bounds__(256) void ff_act_kernel(void) {
    int row = blockIdx.y;
    int j8 = blockIdx.x * 256 + threadIdx.x;     // 8-half chunk index 0..1023
    const __half* prow = g_projh + (size_t)row * FUSED_OUT;
    uint4 xv = *(const uint4*)(prow + FF_BASE + j8 * 8);
    uint4 gv = *(const uint4*)(prow + GATE_BASE + j8 * 8);
    const uint32_t* xp = (const uint32_t*)&xv;
    const uint32_t* gp = (const uint32_t*)&gv;
    uint4 ov;
    uint32_t* op = (uint32_t*)&ov;
    #pragma unroll
    for (int k = 0; k < 4; k++) {
        union { uint32_t u; __half2 h; } xu, gu;
        xu.u = xp[k]; gu.u = gp[k];
        float2 xf = __half22float2(xu.h);
        float2 gf = __half22float2(gu.h);
        float o0 = xf.x * (gf.x / (1.0f + __expf(-gf.x)));
        float o1 = xf.y * (gf.y / (1.0f + __expf(-gf.y)));
        op[k] = h2_u32(__floats2half2_rn(o0, o1));
    }
    *(uint4*)(g_cath + (size_t)row * CAT_K + ATTN_INNER + j8 * 8) = ov;
}

// ------------------------------- launch -------------------------------------
extern "C" void kernel_launch(void* const* d_in, const int* in_sizes, int n_in,
                              void* d_out, int out_size) {
    const float* x          = (const float*)d_in[0];
    const float* gamma      = (const float*)d_in[1];
    const float* w_fused    = (const float*)d_in[2];
    const float* w_attn_out = (const float*)d_in[3];
    const float* w_ff_out   = (const float*)d_in[4];
    float* out = (float*)d_out;

    __half *p_xnh, *p_projh, *p_cath, *p_wfh, *p_wcath;
    cudaGetSymbolAddress((void**)&p_xnh, g_xnh);
    cudaGetSymbolAddress((void**)&p_projh, g_projh);
    cudaGetSymbolAddress((void**)&p_cath, g_cath);
    cudaGetSymbolAddress((void**)&p_wfh, g_wfh);
    cudaGetSymbolAddress((void**)&p_wcath, g_wcath);

    const int SMEM_DYN = NSTG * STAGE;   // 217088 B
    cudaFuncSetAttribute((const void*)mma_gemm<true>,
                         cudaFuncAttributeMaxDynamicSharedMemorySize, SMEM_DYN);
    cudaFuncSetAttribute((const void*)mma_gemm<false>,
                         cudaFuncAttributeMaxDynamicSharedMemorySize, SMEM_DYN);
    cudaFuncSetAttribute((const void*)flash_attn,
                         cudaFuncAttributeMaxDynamicSharedMemorySize, FSMEM);

    // 0. weight fp32->fp16 streaming converts (layout preserved, [K][N])
    wconv_kernel<<<2048, 256>>>(w_fused, p_wfh, (size_t)DIM * FUSED_OUT);
    wconv_kernel<<<1024, 256>>>(w_attn_out, p_wcath, (size_t)ATTN_INNER * DIM);
    wconv_kernel<<<1024, 256>>>(w_ff_out, p_wcath + (size_t)ATTN_INNER * DIM,
                                (size_t)FF_INNER * DIM);

    // 1. LayerNorm -> xn half
    ln_kernel<<<NSEQ, 256>>>(x, gamma);

    // 2. proj = xn @ wf  -> proj half   (wf [2048][18688])
    mma_gemm<true>
        <<<dim3(NSEQ / 256, FUSED_OUT / 128, 1), 256, SMEM_DYN>>>(
        p_xnh, DIM, p_wfh, FUSED_OUT, p_projh, FUSED_OUT, DIM);

    // 3-5. fused flash attention -> cat cols [0,2048)
    flash_attn<<<dim3(NSEQ / 64, HEADS), 128, FSMEM>>>();

    // 6. SwiGLU -> cat cols [2048, 10240)
    ff_act_kernel<<<dim3(FF_INNER / 2048, NSEQ), 256>>>();

    // 7. out = cat @ wcat  (fp32 out; wcat [10240][2048])
    mma_gemm<false>
        <<<dim3(NSEQ / 256, DIM / 128, 1), 256, SMEM_DYN>>>(
        p_cath, CAT_K, p_wcath, DIM, out, DIM, CAT_K);
}